// round 9
// baseline (speedup 1.0000x reference)
#include <cuda_runtime.h>
#include <cuda_bf16.h>
#include <cuda_fp8.h>
#include <math.h>
#include <stdint.h>

// Problem constants (confirmed: inner = DIM_HEAD*dim = 16384)
#define BATCH   2
#define NTOK    2048
#define DIM     256
#define HEADS   8
#define INNER   16384
#define DHEAD   2048
#define TOK     (BATCH*NTOK)      // 4096
#define ATT_SCALE 0.125f
#define LN_EPS  1e-5f
#define NSPLIT  8
#define KS      (DHEAD/NSPLIT)    // 256

// quantization scales (cross products must be equal: sAh*sBl == sAl*sBh)
#define S_HI   16.0f
#define S_LO   4096.0f
#define S_PH   256.0f
#define S_PL   65536.0f
#define S_UH   1.0f
#define S_UL   256.0f
#define CROSSINV (1.0f / 65536.0f)

// ---------------- scratch ---------------------------------------------------
__device__ float g_xn[TOK * DIM];
__device__ float g_pm[(size_t)HEADS * NSPLIT * DIM * DIM];
__device__ float g_pg[(size_t)HEADS * NSPLIT * DIM * DIM];
__device__ float g_t [(size_t)BATCH * HEADS * NTOK * DIM];
__device__ float g_ut[(size_t)BATCH * HEADS * DIM * NTOK];
__device__ float g_s [(size_t)BATCH * NTOK * INNER];
__device__ float g_op[(size_t)BATCH * HEADS * NTOK * DIM];

__device__ __nv_bfloat16 g_xnh[TOK * DIM];
__device__ __nv_bfloat16 g_mth[HEADS * DIM * DIM];
__device__ __nv_bfloat16 g_ghh[HEADS * DIM * DIM];
__device__ __nv_bfloat16 g_th [(size_t)BATCH * HEADS * NTOK * DIM];
__device__ __nv_bfloat16 g_uth[(size_t)BATCH * HEADS * DIM * NTOK];
__device__ __nv_bfloat16 g_ph [(size_t)BATCH * NTOK * INNER];

__device__ uint8_t g_xn8h[TOK * DIM];
__device__ uint8_t g_xn8l[TOK * DIM];
__device__ uint8_t g_mt8h[HEADS * DIM * DIM];
__device__ uint8_t g_mt8l[HEADS * DIM * DIM];
__device__ uint8_t g_g8h [HEADS * DIM * DIM];
__device__ uint8_t g_g8l [HEADS * DIM * DIM];
__device__ uint8_t g_t8h [(size_t)BATCH * HEADS * NTOK * DIM];
__device__ uint8_t g_t8l [(size_t)BATCH * HEADS * NTOK * DIM];
__device__ uint8_t g_ut8h[(size_t)BATCH * HEADS * DIM * NTOK];
__device__ uint8_t g_ut8l[(size_t)BATCH * HEADS * DIM * NTOK];
__device__ uint8_t g_p8h [(size_t)BATCH * NTOK * INNER];
__device__ uint8_t g_p8l [(size_t)BATCH * NTOK * INNER];

// ---------------- asm helpers ------------------------------------------------
__device__ __forceinline__ uint32_t smem_u32(const void* p) {
    uint32_t a;
    asm("{ .reg .u64 tmp; cvta.to.shared.u64 tmp, %1; cvt.u32.u64 %0, tmp; }"
        : "=r"(a) : "l"(p));
    return a;
}
__device__ __forceinline__ void ldsm4u(uint32_t* d, uint32_t a)
{
    asm volatile("ldmatrix.sync.aligned.m8n8.x4.shared.b16 {%0,%1,%2,%3}, [%4];"
                 : "=r"(d[0]), "=r"(d[1]), "=r"(d[2]), "=r"(d[3]) : "r"(a));
}
__device__ __forceinline__ void mma_bf16(float* d, const uint32_t* a, const uint32_t* b)
{
    asm volatile(
        "mma.sync.aligned.m16n8k16.row.col.f32.bf16.bf16.f32 "
        "{%0,%1,%2,%3}, {%4,%5,%6,%7}, {%8,%9}, {%0,%1,%2,%3};"
        : "+f"(d[0]), "+f"(d[1]), "+f"(d[2]), "+f"(d[3])
        : "r"(a[0]), "r"(a[1]), "r"(a[2]), "r"(a[3]), "r"(b[0]), "r"(b[1]));
}
__device__ __forceinline__ void mma_fp8(float* d, const uint32_t* a, const uint32_t* b)
{
    asm volatile(
        "mma.sync.aligned.m16n8k32.row.col.f32.e4m3.e4m3.f32 "
        "{%0,%1,%2,%3}, {%4,%5,%6,%7}, {%8,%9}, {%0,%1,%2,%3};"
        : "+f"(d[0]), "+f"(d[1]), "+f"(d[2]), "+f"(d[3])
        : "r"(a[0]), "r"(a[1]), "r"(a[2]), "r"(a[3]), "r"(b[0]), "r"(b[1]));
}
#define CP16(dst, src) \
    asm volatile("cp.async.cg.shared.global [%0], [%1], 16;" :: "r"(dst), "l"(src))
#define CP_COMMIT() asm volatile("cp.async.commit_group;" ::: "memory")
#define CP_WAIT1()  asm volatile("cp.async.wait_group 1;" ::: "memory")
#define CP_WAIT0()  asm volatile("cp.async.wait_group 0;" ::: "memory")

__device__ __forceinline__ uint32_t pack_fp8x4(float a, float b, float c, float d)
{
    __nv_fp8_e4m3 qa(a), qb(b), qc(c), qd(d);
    return (uint32_t)qa.__x | ((uint32_t)qb.__x << 8) |
           ((uint32_t)qc.__x << 16) | ((uint32_t)qd.__x << 24);
}

// stage layout (bytes): bf16 A (128 rows x 40 elems), bf16 B, 4 fp8 tiles (128 x 48B)
#define OFF_AH  0
#define OFF_BH  10240
#define OFF_A8H 20480
#define OFF_A8L 26624
#define OFF_B8H 32768
#define OFF_B8L 38912
#define STAGEB  45056
#define MM_SMEM (2 * STAGEB)

// ---------------- mixed bf16 + fp8 NT GEMM ----------------------------------
// C[m][n] = alpha * ( Ahi.Bhi  +  crossinv * (A8h.B8l + A8l.B8h) )
// A row-major (M,K), B row-major (N,K). Block 128x128, 8 warps of 32x64, k32 chunks.
__global__ void __launch_bounds__(256, 1)
mma_mixed(const __nv_bfloat16* __restrict__ Ahi, const uint8_t* __restrict__ A8h,
          const uint8_t* __restrict__ A8l,
          const __nv_bfloat16* __restrict__ Bhi, const uint8_t* __restrict__ B8h,
          const uint8_t* __restrict__ B8l,
          float* __restrict__ C,
          int K, int lda, int ldb, int ldc,
          int hdiv,
          long long sAb, long long sAh,
          long long sBb, long long sBh,
          long long sCb, long long sCh,
          float alpha, float crossinv)
{
    extern __shared__ __align__(16) char smem[];
    uint32_t sb = smem_u32(smem);

    int bz = blockIdx.z;
    int zb = bz / hdiv, zh = bz % hdiv;
    long long aoff = (long long)zb * sAb + (long long)zh * sAh;
    long long boff = (long long)zb * sBb + (long long)zh * sBh;
    const __nv_bfloat16* Ah = Ahi + aoff;
    const uint8_t*       A8hp = A8h + aoff;
    const uint8_t*       A8lp = A8l + aoff;
    const __nv_bfloat16* Bh = Bhi + boff;
    const uint8_t*       B8hp = B8h + boff;
    const uint8_t*       B8lp = B8l + boff;
    float* Cb = C + (long long)zb * sCb + (long long)zh * sCh;

    int m0 = blockIdx.y * 128;
    int n0 = blockIdx.x * 128;
    int tid  = threadIdx.x;
    int warp = tid >> 5;
    int lane = tid & 31;
    int wm = (warp & 3) * 32;
    int wn = (warp >> 2) * 64;

    // loader indices
    int r  = tid >> 2;            // 0..63   bf16: rows r, r+64, 16B each
    int kc = (tid & 3) * 8;       // bf16 col (elements)
    int r2 = tid >> 1;            // 0..127  fp8: one row, one 16B half
    int hf = (tid & 1) * 16;      // fp8 col (bytes)

    float acc [2][8][4];
    float acc2[2][8][4];
    #pragma unroll
    for (int i = 0; i < 2; i++)
        #pragma unroll
        for (int j = 0; j < 8; j++)
            #pragma unroll
            for (int c = 0; c < 4; c++) { acc[i][j][c] = 0.f; acc2[i][j][c] = 0.f; }

    const int NC = K / 32;

    // ---- stage loader (cp.async) ----
    auto load_stage = [&](int st, int k0) {
        uint32_t s0 = sb + (uint32_t)st * STAGEB;
        #pragma unroll
        for (int i = 0; i < 2; i++) {
            int row = r + i * 64;
            CP16(s0 + OFF_AH + row * 80 + kc * 2,
                 Ah + (long long)(m0 + row) * lda + k0 + kc);
            CP16(s0 + OFF_BH + row * 80 + kc * 2,
                 Bh + (long long)(n0 + row) * ldb + k0 + kc);
        }
        CP16(s0 + OFF_A8H + r2 * 48 + hf, A8hp + (long long)(m0 + r2) * lda + k0 + hf);
        CP16(s0 + OFF_A8L + r2 * 48 + hf, A8lp + (long long)(m0 + r2) * lda + k0 + hf);
        CP16(s0 + OFF_B8H + r2 * 48 + hf, B8hp + (long long)(n0 + r2) * ldb + k0 + hf);
        CP16(s0 + OFF_B8L + r2 * 48 + hf, B8lp + (long long)(n0 + r2) * ldb + k0 + hf);
    };

    load_stage(0, 0);
    CP_COMMIT();

    for (int i = 0; i < NC; i++) {
        int st = i & 1;
        if (i + 1 < NC) { load_stage(st ^ 1, (i + 1) * 32); CP_COMMIT(); CP_WAIT1(); }
        else            { CP_WAIT0(); }
        __syncthreads();

        uint32_t base = sb + (uint32_t)st * STAGEB;

        // ---- fp8 A fragments (k0-31 in one x4 per m-tile) ----
        uint32_t a8h[2][4], a8l[2][4];
        #pragma unroll
        for (int ii = 0; ii < 2; ii++) {
            uint32_t ra = (uint32_t)(wm + ii * 16 + (lane & 15)) * 48 + ((lane >> 4) << 4);
            ldsm4u(a8h[ii], base + OFF_A8H + ra);
            ldsm4u(a8l[ii], base + OFF_A8L + ra);
        }

        // ---- bf16 hh passes (two k16 halves) ----
        #pragma unroll
        for (int s = 0; s < 32; s += 16) {
            uint32_t ah[2][4];
            #pragma unroll
            for (int ii = 0; ii < 2; ii++) {
                uint32_t ra = (uint32_t)(wm + ii * 16 + (lane & 15)) * 80
                            + (uint32_t)(s + ((lane >> 4) << 3)) * 2;
                ldsm4u(ah[ii], base + OFF_AH + ra);
            }
            #pragma unroll
            for (int j = 0; j < 4; j++) {
                uint32_t rb = (uint32_t)(wn + j * 16 + ((lane >> 4) << 3) + (lane & 7)) * 80
                            + (uint32_t)(s + ((lane >> 3) & 1) * 8) * 2;
                uint32_t bh[4];
                ldsm4u(bh, base + OFF_BH + rb);
                #pragma unroll
                for (int jj = 0; jj < 2; jj++)
                    #pragma unroll
                    for (int ii = 0; ii < 2; ii++)
                        mma_bf16(acc[ii][j * 2 + jj], ah[ii], bh + jj * 2);
            }
        }

        // ---- fp8 cross passes (full k32 per mma) ----
        #pragma unroll
        for (int j = 0; j < 4; j++) {
            uint32_t rb = (uint32_t)(wn + j * 16 + ((lane >> 4) << 3) + (lane & 7)) * 48
                        + ((lane >> 3) & 1) * 16;
            uint32_t b8h[4], b8l[4];
            ldsm4u(b8h, base + OFF_B8H + rb);
            ldsm4u(b8l, base + OFF_B8L + rb);
            #pragma unroll
            for (int jj = 0; jj < 2; jj++)
                #pragma unroll
                for (int ii = 0; ii < 2; ii++) {
                    mma_fp8(acc2[ii][j * 2 + jj], a8h[ii], b8l + jj * 2);
                    mma_fp8(acc2[ii][j * 2 + jj], a8l[ii], b8h + jj * 2);
                }
        }
        __syncthreads();
    }

    // ---- epilogue ----
    #pragma unroll
    for (int i = 0; i < 2; i++) {
        #pragma unroll
        for (int j = 0; j < 8; j++) {
            int row = m0 + wm + i * 16 + (lane >> 2);
            int col = n0 + wn + j * 8 + (lane & 3) * 2;
            float2 v0, v1;
            v0.x = alpha * (acc[i][j][0] + crossinv * acc2[i][j][0]);
            v0.y = alpha * (acc[i][j][1] + crossinv * acc2[i][j][1]);
            v1.x = alpha * (acc[i][j][2] + crossinv * acc2[i][j][2]);
            v1.y = alpha * (acc[i][j][3] + crossinv * acc2[i][j][3]);
            *(float2*)(Cb + (long long)row * ldc + col)       = v0;
            *(float2*)(Cb + (long long)(row + 8) * ldc + col) = v1;
        }
    }
}

// ---------------- LayerNorm -------------------------------------------------
__global__ void ln_kernel(const float* __restrict__ x,
                          const float* __restrict__ gamma,
                          float* __restrict__ xn)
{
    int row = blockIdx.x;
    int t   = threadIdx.x;
    float v = x[row * DIM + t];

    __shared__ float s1[8], s2[8];
    float a = v, b = v * v;
    #pragma unroll
    for (int o = 16; o > 0; o >>= 1) {
        a += __shfl_xor_sync(0xffffffffu, a, o);
        b += __shfl_xor_sync(0xffffffffu, b, o);
    }
    int lane = t & 31, w = t >> 5;
    if (lane == 0) { s1[w] = a; s2[w] = b; }
    __syncthreads();
    if (t == 0) {
        float sa = 0.f, sb = 0.f;
        #pragma unroll
        for (int i = 0; i < 8; i++) { sa += s1[i]; sb += s2[i]; }
        s1[0] = sa * (1.0f / DIM);
        s2[0] = sb * (1.0f / DIM);
    }
    __syncthreads();
    float mu  = s1[0];
    float var = s2[0] - mu * mu;
    float rr  = rsqrtf(var + LN_EPS);
    xn[row * DIM + t] = (v - mu) * rr * (gamma[t] + 1.0f);
}

// ------------ fp32 -> bf16 hi + fp8 hi/lo quantization ----------------------
__global__ void quant_kernel(const float* __restrict__ src,
                             __nv_bfloat16* __restrict__ hi,
                             uint8_t* __restrict__ f8h,
                             uint8_t* __restrict__ f8l,
                             long long n4, float sh, float sl)
{
    long long i = ((long long)blockIdx.x * blockDim.x + threadIdx.x);
    if (i >= n4) return;
    long long e = i * 4;
    float4 v = *(const float4*)(src + e);
    __nv_bfloat16 h0 = __float2bfloat16(v.x);
    __nv_bfloat16 h1 = __float2bfloat16(v.y);
    __nv_bfloat16 h2 = __float2bfloat16(v.z);
    __nv_bfloat16 h3 = __float2bfloat16(v.w);
    ((__nv_bfloat162*)(hi + e))[0] = __nv_bfloat162{h0, h1};
    ((__nv_bfloat162*)(hi + e))[1] = __nv_bfloat162{h2, h3};
    *(uint32_t*)(f8h + e) = pack_fp8x4(v.x * sh, v.y * sh, v.z * sh, v.w * sh);
    float l0 = (v.x - __bfloat162float(h0)) * sl;
    float l1 = (v.y - __bfloat162float(h1)) * sl;
    float l2 = (v.z - __bfloat162float(h2)) * sl;
    float l3 = (v.w - __bfloat162float(h3)) * sl;
    *(uint32_t*)(f8l + e) = pack_fp8x4(l0, l1, l2, l3);
}

// ---------------- split-K 64x64 GEMM for head precomputes --------------------
template<bool AT>
__global__ void __launch_bounds__(256)
gemm64_sk(const float* __restrict__ A, const float* __restrict__ B,
          float* __restrict__ Cp, int lda, int ldb)
{
    __shared__ float As[16][68];
    __shared__ float Bs[16][68];

    int z = blockIdx.z;
    int h = z / NSPLIT, sp = z % NSPLIT;
    long long hk0 = (long long)h * DHEAD + (long long)sp * KS;

    const float* Ab = AT ? (A + hk0 * lda) : (A + hk0);
    const float* Bb = B + hk0 * ldb;
    float* Cb = Cp + (long long)z * DIM * DIM;

    int m0 = blockIdx.y * 64;
    int n0 = blockIdx.x * 64;
    int tid = threadIdx.x;
    int tx = tid & 15;
    int ty = tid >> 4;

    float acc[4][4];
    #pragma unroll
    for (int i = 0; i < 4; i++)
        #pragma unroll
        for (int j = 0; j < 4; j++) acc[i][j] = 0.f;

    for (int k0 = 0; k0 < KS; k0 += 16) {
        if (AT) {
            int kk  = tid >> 4;
            int mm4 = (tid & 15) << 2;
            float4 a = *(const float4*)(Ab + (long long)(k0 + kk) * lda + m0 + mm4);
            *(float4*)&As[kk][mm4] = a;
        } else {
            int mm = tid >> 2;
            int kq = (tid & 3) << 2;
            float4 a = *(const float4*)(Ab + (long long)(m0 + mm) * lda + k0 + kq);
            As[kq + 0][mm] = a.x;
            As[kq + 1][mm] = a.y;
            As[kq + 2][mm] = a.z;
            As[kq + 3][mm] = a.w;
        }
        {
            int kk  = tid >> 4;
            int nn4 = (tid & 15) << 2;
            float4 b = *(const float4*)(Bb + (long long)(k0 + kk) * ldb + n0 + nn4);
            *(float4*)&Bs[kk][nn4] = b;
        }
        __syncthreads();

        #pragma unroll
        for (int kk = 0; kk < 16; kk++) {
            float ra[4], rb[4];
            #pragma unroll
            for (int i = 0; i < 4; i++) ra[i] = As[kk][ty * 4 + i];
            #pragma unroll
            for (int j = 0; j < 4; j++) rb[j] = Bs[kk][tx * 4 + j];
            #pragma unroll
            for (int i = 0; i < 4; i++)
                #pragma unroll
                for (int j = 0; j < 4; j++)
                    acc[i][j] = fmaf(ra[i], rb[j], acc[i][j]);
        }
        __syncthreads();
    }

    #pragma unroll
    for (int i = 0; i < 4; i++)
        #pragma unroll
        for (int j = 0; j < 4; j++)
            Cb[(long long)(m0 + ty * 4 + i) * DIM + (n0 + tx * 4 + j)] = acc[i][j];
}

// ------------- reduce split-K partials -> bf16 hi + fp8 hi/lo ----------------
__global__ void reduce_split_kernel(const float* __restrict__ part,
                                    __nv_bfloat16* __restrict__ hi,
                                    uint8_t* __restrict__ f8h,
                                    uint8_t* __restrict__ f8l,
                                    float sh, float sl)
{
    int idx = blockIdx.x * 256 + threadIdx.x;
    int h   = idx >> 16;
    int off = idx & 65535;
    const float* p = part + (long long)h * NSPLIT * 65536 + off;
    float acc = 0.f;
    #pragma unroll
    for (int s = 0; s < NSPLIT; s++) acc += p[(long long)s * 65536];
    __nv_bfloat16 hv = __float2bfloat16(acc);
    hi[idx] = hv;
    __nv_fp8_e4m3 qh(acc * sh);
    __nv_fp8_e4m3 ql((acc - __bfloat162float(hv)) * sl);
    f8h[idx] = qh.__x;
    f8l[idx] = ql.__x;
}

// ------------- row softmax (2048 cols) -> bf16 hi + fp8 hi/lo ----------------
__global__ void softmax_split_kernel(const float* __restrict__ S,
                                     __nv_bfloat16* __restrict__ Phi,
                                     uint8_t* __restrict__ P8h,
                                     uint8_t* __restrict__ P8l)
{
    size_t row = blockIdx.x;
    const float* sr = S + row * (size_t)NTOK;
    int t = threadIdx.x;

    float v[8];
    float m = -1e30f;
    #pragma unroll
    for (int i = 0; i < 8; i++) {
        v[i] = sr[t + 256 * i];
        m = fmaxf(m, v[i]);
    }

    __shared__ float sred[8];
    float w = m;
    #pragma unroll
    for (int o = 16; o > 0; o >>= 1) w = fmaxf(w, __shfl_xor_sync(0xffffffffu, w, o));
    if ((t & 31) == 0) sred[t >> 5] = w;
    __syncthreads();
    if (t == 0) {
        float z = sred[0];
        #pragma unroll
        for (int i = 1; i < 8; i++) z = fmaxf(z, sred[i]);
        sred[0] = z;
    }
    __syncthreads();
    m = sred[0];
    __syncthreads();

    float sum = 0.f;
    #pragma unroll
    for (int i = 0; i < 8; i++) {
        v[i] = __expf(v[i] - m);
        sum += v[i];
    }
    float w2 = sum;
    #pragma unroll
    for (int o = 16; o > 0; o >>= 1) w2 += __shfl_xor_sync(0xffffffffu, w2, o);
    if ((t & 31) == 0) sred[t >> 5] = w2;
    __syncthreads();
    if (t == 0) {
        float z = 0.f;
        #pragma unroll
        for (int i = 0; i < 8; i++) z += sred[i];
        sred[0] = z;
    }
    __syncthreads();
    float inv = 1.0f / sred[0];

    size_t base = row * (size_t)NTOK;
    #pragma unroll
    for (int i = 0; i < 8; i++) {
        float p = v[i] * inv;
        __nv_bfloat16 h = __float2bfloat16(p);
        Phi[base + t + 256 * i] = h;
        __nv_fp8_e4m3 qh(p * S_PH);
        __nv_fp8_e4m3 ql((p - __bfloat162float(h)) * S_PL);
        P8h[base + t + 256 * i] = qh.__x;
        P8l[base + t + 256 * i] = ql.__x;
    }
}

// ---------------- reduce per-head partials ----------------------------------
__global__ void reduce_kernel(const float* __restrict__ op, float* __restrict__ out)
{
    int row = blockIdx.x;
    int t   = threadIdx.x;
    int b   = row >> 11;
    int q   = row & 2047;
    const float* base = op + (((long long)b * HEADS) * NTOK + q) * DIM + t;
    float acc = 0.f;
    #pragma unroll
    for (int h = 0; h < HEADS; h++)
        acc += base[(long long)h * NTOK * DIM];
    out[(long long)row * DIM + t] = acc;
}

// ---------------- launch ----------------------------------------------------
extern "C" void kernel_launch(void* const* d_in, const int* in_sizes, int n_in,
                              void* d_out, int out_size)
{
    const float* x     = (const float*)d_in[0];
    const float* gamma = (const float*)d_in[1];
    const float* Wq    = (const float*)d_in[2];
    const float* Wk    = (const float*)d_in[3];
    const float* Wv    = (const float*)d_in[4];
    const float* Wo    = (const float*)d_in[5];
    float* out = (float*)d_out;

    cudaFuncSetAttribute(mma_mixed, cudaFuncAttributeMaxDynamicSharedMemorySize, MM_SMEM);

    float *xn, *pm, *pg, *tt, *ut, *s, *op;
    __nv_bfloat16 *xnh, *mth, *ghh, *th, *uth, *ph;
    uint8_t *xn8h, *xn8l, *mt8h, *mt8l, *g8h, *g8l, *t8h, *t8l, *ut8h, *ut8l, *p8h, *p8l;
    cudaGetSymbolAddress((void**)&xn,  g_xn);
    cudaGetSymbolAddress((void**)&pm,  g_pm);
    cudaGetSymbolAddress((void**)&pg,  g_pg);
    cudaGetSymbolAddress((void**)&tt,  g_t);
    cudaGetSymbolAddress((void**)&ut,  g_ut);
    cudaGetSymbolAddress((void**)&s,   g_s);
    cudaGetSymbolAddress((void**)&op,  g_op);
    cudaGetSymbolAddress((void**)&xnh, g_xnh);
    cudaGetSymbolAddress((void**)&mth, g_mth);
    cudaGetSymbolAddress((void**)&ghh, g_ghh);
    cudaGetSymbolAddress((void**)&th,  g_th);
    cudaGetSymbolAddress((void**)&uth, g_uth);
    cudaGetSymbolAddress((void**)&ph,  g_ph);
    cudaGetSymbolAddress((void**)&xn8h, g_xn8h);
    cudaGetSymbolAddress((void**)&xn8l, g_xn8l);
    cudaGetSymbolAddress((void**)&mt8h, g_mt8h);
    cudaGetSymbolAddress((void**)&mt8l, g_mt8l);
    cudaGetSymbolAddress((void**)&g8h,  g_g8h);
    cudaGetSymbolAddress((void**)&g8l,  g_g8l);
    cudaGetSymbolAddress((void**)&t8h,  g_t8h);
    cudaGetSymbolAddress((void**)&t8l,  g_t8l);
    cudaGetSymbolAddress((void**)&ut8h, g_ut8h);
    cudaGetSymbolAddress((void**)&ut8l, g_ut8l);
    cudaGetSymbolAddress((void**)&p8h,  g_p8h);
    cudaGetSymbolAddress((void**)&p8l,  g_p8l);

    const long long TD  = (long long)NTOK * DIM;
    const long long HTD = (long long)HEADS * TD;
    const long long SB  = (long long)NTOK * INNER;
    const long long DD  = (long long)DIM * DIM;

    // 1) LayerNorm + quantize xn
    ln_kernel<<<TOK, 256>>>(x, gamma, xn);
    quant_kernel<<<(TOK * DIM / 4 + 255) / 256, 256>>>(xn, xnh, xn8h, xn8l,
                                                       TOK * DIM / 4, S_HI, S_LO);

    // 2) precomputes (split-K): Mt_h = Wk_h^T Wq_h ; G_h = Wo_h Wv_h
    {
        dim3 grid(4, 4, HEADS * NSPLIT);
        gemm64_sk<true ><<<grid, 256>>>(Wk, Wq, pm, DIM, DIM);
        gemm64_sk<false><<<grid, 256>>>(Wo, Wv, pg, INNER, DIM);
        reduce_split_kernel<<<HEADS * DIM * DIM / 256, 256>>>(pm, mth, mt8h, mt8l, S_HI, S_LO);
        reduce_split_kernel<<<HEADS * DIM * DIM / 256, 256>>>(pg, ghh, g8h, g8l, S_HI, S_LO);
    }

    // 3) T[b][h] = xn_b * Mt_h^T  (mixed NT), then quantize
    {
        dim3 grid(DIM / 128, NTOK / 128, BATCH * HEADS);
        mma_mixed<<<grid, 256, MM_SMEM>>>(
            xnh, xn8h, xn8l, mth, mt8h, mt8l, tt,
            DIM, DIM, DIM, DIM, HEADS,
            TD, 0, 0, DD, HTD, TD, 1.0f, CROSSINV);
    }
    quant_kernel<<<(int)((BATCH * HTD / 4 + 255) / 256), 256>>>(tt, th, t8h, t8l,
                                                                BATCH * HTD / 4, S_HI, S_LO);

    // 4) S = scale * T * xn^T  (mixed NT)
    {
        dim3 grid(NTOK / 128, NTOK / 128, BATCH * HEADS);
        mma_mixed<<<grid, 256, MM_SMEM>>>(
            th, t8h, t8l, xnh, xn8h, xn8l, s,
            DIM, DIM, DIM, INNER, HEADS,
            HTD, TD, TD, 0, SB, (long long)DHEAD,
            ATT_SCALE, CROSSINV);
    }

    // 5) softmax + P quantize
    softmax_split_kernel<<<BATCH * NTOK * HEADS, 256>>>(s, ph, p8h, p8l);

    // 6) Ut[b][h] = G_h * xn_b^T  (mixed NT), then quantize (U scales)
    {
        dim3 grid(NTOK / 128, DIM / 128, BATCH * HEADS);
        mma_mixed<<<grid, 256, MM_SMEM>>>(
            ghh, g8h, g8l, xnh, xn8h, xn8l, ut,
            DIM, DIM, DIM, NTOK, HEADS,
            0, DD, TD, 0, HTD, TD, 1.0f, CROSSINV);
    }
    quant_kernel<<<(int)((BATCH * HTD / 4 + 255) / 256), 256>>>(ut, uth, ut8h, ut8l,
                                                                BATCH * HTD / 4, S_UH, S_UL);

    // 7) op[b][h] = P[b][h] * Ut[b][h]^T  (mixed NT; Ph8*Ul8 + Pl8*Uh8, both 2^16)
    {
        dim3 grid(DIM / 128, NTOK / 128, BATCH * HEADS);
        mma_mixed<<<grid, 256, MM_SMEM>>>(
            ph, p8h, p8l, uth, ut8h, ut8l, op,
            NTOK, INNER, NTOK, DIM, HEADS,
            SB, (long long)DHEAD, HTD, TD, HTD, TD,
            1.0f, CROSSINV);
    }

    // 8) out = sum_h op[b][h]
    reduce_kernel<<<TOK, 256>>>(op, out);
}

// round 10
// speedup vs baseline: 1.3495x; 1.3495x over previous
#include <cuda_runtime.h>
#include <cuda_bf16.h>
#include <math.h>
#include <stdint.h>

// Problem constants (confirmed: inner = DIM_HEAD*dim = 16384)
#define BATCH   2
#define NTOK    2048
#define DIM     256
#define HEADS   8
#define INNER   16384
#define DHEAD   2048
#define TOK     (BATCH*NTOK)      // 4096
#define ATT_SCALE 0.125f
#define LN_EPS  1e-5f
#define NSPLIT  8
#define KS      (DHEAD/NSPLIT)    // 256

// ---------------- scratch ---------------------------------------------------
__device__ float g_xn[TOK * DIM];
__device__ float g_pm[(size_t)HEADS * NSPLIT * DIM * DIM];
__device__ float g_pg[(size_t)HEADS * NSPLIT * DIM * DIM];
__device__ float g_t [(size_t)BATCH * HEADS * NTOK * DIM];
__device__ float g_ut[(size_t)BATCH * HEADS * DIM * NTOK];
__device__ float g_s [(size_t)BATCH * NTOK * INNER];
__device__ float g_op[(size_t)BATCH * HEADS * NTOK * DIM];

__device__ __nv_bfloat16 g_xnh[TOK * DIM];
__device__ __nv_bfloat16 g_xnl[TOK * DIM];
__device__ __nv_bfloat16 g_mth[HEADS * DIM * DIM];
__device__ __nv_bfloat16 g_mtl[HEADS * DIM * DIM];
__device__ __nv_bfloat16 g_gh_[HEADS * DIM * DIM];
__device__ __nv_bfloat16 g_gl_[HEADS * DIM * DIM];
__device__ __nv_bfloat16 g_th [(size_t)BATCH * HEADS * NTOK * DIM];
__device__ __nv_bfloat16 g_tl [(size_t)BATCH * HEADS * NTOK * DIM];
__device__ __nv_bfloat16 g_uth[(size_t)BATCH * HEADS * DIM * NTOK];
__device__ __nv_bfloat16 g_utl[(size_t)BATCH * HEADS * DIM * NTOK];
__device__ __nv_bfloat16 g_ph [(size_t)BATCH * NTOK * INNER];
__device__ __nv_bfloat16 g_pl [(size_t)BATCH * NTOK * INNER];

// ---------------- asm helpers ------------------------------------------------
__device__ __forceinline__ uint32_t smem_u32(const void* p) {
    uint32_t a;
    asm("{ .reg .u64 tmp; cvta.to.shared.u64 tmp, %1; cvt.u32.u64 %0, tmp; }"
        : "=r"(a) : "l"(p));
    return a;
}
__device__ __forceinline__ void ldsm4u(uint32_t* d, uint32_t a)
{
    asm volatile("ldmatrix.sync.aligned.m8n8.x4.shared.b16 {%0,%1,%2,%3}, [%4];"
                 : "=r"(d[0]), "=r"(d[1]), "=r"(d[2]), "=r"(d[3]) : "r"(a));
}
__device__ __forceinline__ void mma_bf16(float* d, const uint32_t* a, const uint32_t* b)
{
    asm volatile(
        "mma.sync.aligned.m16n8k16.row.col.f32.bf16.bf16.f32 "
        "{%0,%1,%2,%3}, {%4,%5,%6,%7}, {%8,%9}, {%0,%1,%2,%3};"
        : "+f"(d[0]), "+f"(d[1]), "+f"(d[2]), "+f"(d[3])
        : "r"(a[0]), "r"(a[1]), "r"(a[2]), "r"(a[3]), "r"(b[0]), "r"(b[1]));
}
#define CP16(dst, src) \
    asm volatile("cp.async.cg.shared.global [%0], [%1], 16;" :: "r"(dst), "l"(src))
#define CP_COMMIT() asm volatile("cp.async.commit_group;" ::: "memory")
#define CP_WAIT1()  asm volatile("cp.async.wait_group 1;" ::: "memory")
#define CP_WAIT0()  asm volatile("cp.async.wait_group 0;" ::: "memory")

// stage layout (bytes): 4 tiles of 128 rows x 40 bf16 (80B rows, conflict-free for ldmatrix)
#define OFF_AH  0
#define OFF_AL  10240
#define OFF_BH  20480
#define OFF_BL  30720
#define STAGE   40960
#define MM_SMEM (2 * STAGE)

// ---------------- bf16 split tensor-core GEMM (NT), cp.async 2-stage --------
// C[m][n] = alpha * sum_k (Ahi*Bhi + Ahi*Blo + Alo*Bhi)[m][k][n]
// A row-major (M,K), B row-major (N,K), bf16; C fp32.
// Block 128x128, 8 warps of 32x64, k-chunk 32.
__global__ void __launch_bounds__(256, 2)
mma_nt(const __nv_bfloat16* __restrict__ Ahi, const __nv_bfloat16* __restrict__ Alo,
       const __nv_bfloat16* __restrict__ Bhi, const __nv_bfloat16* __restrict__ Blo,
       float* __restrict__ C,
       int K, int lda, int ldb, int ldc,
       int hdiv,
       long long sAb, long long sAh,
       long long sBb, long long sBh,
       long long sCb, long long sCh,
       float alpha)
{
    extern __shared__ __align__(16) char smem[];
    uint32_t sb = smem_u32(smem);

    int bz = blockIdx.z;
    int zb = bz / hdiv, zh = bz % hdiv;
    long long aoff = (long long)zb * sAb + (long long)zh * sAh;
    long long boff = (long long)zb * sBb + (long long)zh * sBh;
    const __nv_bfloat16* Ah = Ahi + aoff;
    const __nv_bfloat16* Al = Alo + aoff;
    const __nv_bfloat16* Bh = Bhi + boff;
    const __nv_bfloat16* Bl = Blo + boff;
    float* Cb = C + (long long)zb * sCb + (long long)zh * sCh;

    int m0 = blockIdx.y * 128;
    int n0 = blockIdx.x * 128;
    int tid  = threadIdx.x;
    int warp = tid >> 5;
    int lane = tid & 31;
    int wm = (warp & 3) * 32;
    int wn = (warp >> 2) * 64;

    int r  = tid >> 2;            // 0..63 (rows r and r+64)
    int kc = (tid & 3) * 8;       // k element offset (16B)

    float acc[2][8][4];
    #pragma unroll
    for (int i = 0; i < 2; i++)
        #pragma unroll
        for (int j = 0; j < 8; j++)
            #pragma unroll
            for (int c = 0; c < 4; c++) acc[i][j][c] = 0.f;

    const int NC = K / 32;

    // ---- stage loader (cp.async, 8 x 16B per thread) ----
    auto load_stage = [&](int st, int k0) {
        uint32_t s0 = sb + (uint32_t)st * STAGE;
        #pragma unroll
        for (int i = 0; i < 2; i++) {
            int row = r + i * 64;
            uint32_t so = (uint32_t)row * 80 + (uint32_t)kc * 2;
            CP16(s0 + OFF_AH + so, Ah + (long long)(m0 + row) * lda + k0 + kc);
            CP16(s0 + OFF_AL + so, Al + (long long)(m0 + row) * lda + k0 + kc);
            CP16(s0 + OFF_BH + so, Bh + (long long)(n0 + row) * ldb + k0 + kc);
            CP16(s0 + OFF_BL + so, Bl + (long long)(n0 + row) * ldb + k0 + kc);
        }
    };

    load_stage(0, 0);
    CP_COMMIT();

    for (int i = 0; i < NC; i++) {
        // buffer (i+1)&1 was consumed in iter i-1; end-of-iter sync protects reuse
        if (i + 1 < NC) { load_stage((i + 1) & 1, (i + 1) * 32); CP_COMMIT(); CP_WAIT1(); }
        else            { CP_WAIT0(); }
        __syncthreads();

        uint32_t base = sb + (uint32_t)(i & 1) * STAGE;

        #pragma unroll
        for (int s = 0; s < 32; s += 16) {
            uint32_t ah[2][4], al[2][4];
            #pragma unroll
            for (int ii = 0; ii < 2; ii++) {
                uint32_t ra = base + (uint32_t)(wm + ii * 16 + (lane & 15)) * 80
                            + (uint32_t)(s + ((lane >> 4) << 3)) * 2;
                ldsm4u(ah[ii], ra + OFF_AH);
                ldsm4u(al[ii], ra + OFF_AL);
            }
            #pragma unroll
            for (int j = 0; j < 4; j++) {
                uint32_t rb = base + (uint32_t)(wn + j * 16 + ((lane >> 4) << 3) + (lane & 7)) * 80
                            + (uint32_t)(s + ((lane >> 3) & 1) * 8) * 2;
                uint32_t bh[4], bl[4];
                ldsm4u(bh, rb + OFF_BH);
                ldsm4u(bl, rb + OFF_BL);
                #pragma unroll
                for (int jj = 0; jj < 2; jj++) {
                    #pragma unroll
                    for (int ii = 0; ii < 2; ii++) {
                        mma_bf16(acc[ii][j * 2 + jj], ah[ii], bh + jj * 2);
                        mma_bf16(acc[ii][j * 2 + jj], ah[ii], bl + jj * 2);
                        mma_bf16(acc[ii][j * 2 + jj], al[ii], bh + jj * 2);
                    }
                }
            }
        }
        __syncthreads();   // protects buffer (i&1) before iter i+1 reloads it
    }

    #pragma unroll
    for (int i = 0; i < 2; i++) {
        #pragma unroll
        for (int j = 0; j < 8; j++) {
            int row = m0 + wm + i * 16 + (lane >> 2);
            int col = n0 + wn + j * 8 + (lane & 3) * 2;
            float2 v0 = { alpha * acc[i][j][0], alpha * acc[i][j][1] };
            float2 v1 = { alpha * acc[i][j][2], alpha * acc[i][j][3] };
            *(float2*)(Cb + (long long)row * ldc + col)       = v0;
            *(float2*)(Cb + (long long)(row + 8) * ldc + col) = v1;
        }
    }
}

// ---------------- LayerNorm -------------------------------------------------
__global__ void ln_kernel(const float* __restrict__ x,
                          const float* __restrict__ gamma,
                          float* __restrict__ xn)
{
    int row = blockIdx.x;
    int t   = threadIdx.x;
    float v = x[row * DIM + t];

    __shared__ float s1[8], s2[8];
    float a = v, b = v * v;
    #pragma unroll
    for (int o = 16; o > 0; o >>= 1) {
        a += __shfl_xor_sync(0xffffffffu, a, o);
        b += __shfl_xor_sync(0xffffffffu, b, o);
    }
    int lane = t & 31, w = t >> 5;
    if (lane == 0) { s1[w] = a; s2[w] = b; }
    __syncthreads();
    if (t == 0) {
        float sa = 0.f, sb = 0.f;
        #pragma unroll
        for (int i = 0; i < 8; i++) { sa += s1[i]; sb += s2[i]; }
        s1[0] = sa * (1.0f / DIM);
        s2[0] = sb * (1.0f / DIM);
    }
    __syncthreads();
    float mu  = s1[0];
    float var = s2[0] - mu * mu;
    float rr  = rsqrtf(var + LN_EPS);
    xn[row * DIM + t] = (v - mu) * rr * (gamma[t] + 1.0f);
}

// ---------------- fp32 -> bf16 hi/lo split ----------------------------------
__global__ void split_kernel(const float* __restrict__ src,
                             __nv_bfloat16* __restrict__ hi,
                             __nv_bfloat16* __restrict__ lo,
                             long long n4)
{
    long long i = ((long long)blockIdx.x * blockDim.x + threadIdx.x);
    if (i >= n4) return;
    long long e = i * 4;
    float4 v = *(const float4*)(src + e);
    __nv_bfloat16 h0 = __float2bfloat16(v.x);
    __nv_bfloat16 h1 = __float2bfloat16(v.y);
    __nv_bfloat16 h2 = __float2bfloat16(v.z);
    __nv_bfloat16 h3 = __float2bfloat16(v.w);
    __nv_bfloat16 l0 = __float2bfloat16(v.x - __bfloat162float(h0));
    __nv_bfloat16 l1 = __float2bfloat16(v.y - __bfloat162float(h1));
    __nv_bfloat16 l2 = __float2bfloat16(v.z - __bfloat162float(h2));
    __nv_bfloat16 l3 = __float2bfloat16(v.w - __bfloat162float(h3));
    ((__nv_bfloat162*)(hi + e))[0] = __nv_bfloat162{h0, h1};
    ((__nv_bfloat162*)(hi + e))[1] = __nv_bfloat162{h2, h3};
    ((__nv_bfloat162*)(lo + e))[0] = __nv_bfloat162{l0, l1};
    ((__nv_bfloat162*)(lo + e))[1] = __nv_bfloat162{l2, l3};
}

// ---------------- split-K 64x64 GEMM for head precomputes --------------------
template<bool AT>
__global__ void __launch_bounds__(256)
gemm64_sk(const float* __restrict__ A, const float* __restrict__ B,
          float* __restrict__ Cp, int lda, int ldb)
{
    __shared__ float As[16][68];
    __shared__ float Bs[16][68];

    int z = blockIdx.z;
    int h = z / NSPLIT, sp = z % NSPLIT;
    long long hk0 = (long long)h * DHEAD + (long long)sp * KS;

    const float* Ab = AT ? (A + hk0 * lda) : (A + hk0);
    const float* Bb = B + hk0 * ldb;
    float* Cb = Cp + (long long)z * DIM * DIM;

    int m0 = blockIdx.y * 64;
    int n0 = blockIdx.x * 64;
    int tid = threadIdx.x;
    int tx = tid & 15;
    int ty = tid >> 4;

    float acc[4][4];
    #pragma unroll
    for (int i = 0; i < 4; i++)
        #pragma unroll
        for (int j = 0; j < 4; j++) acc[i][j] = 0.f;

    for (int k0 = 0; k0 < KS; k0 += 16) {
        if (AT) {
            int kk  = tid >> 4;
            int mm4 = (tid & 15) << 2;
            float4 a = *(const float4*)(Ab + (long long)(k0 + kk) * lda + m0 + mm4);
            *(float4*)&As[kk][mm4] = a;
        } else {
            int mm = tid >> 2;
            int kq = (tid & 3) << 2;
            float4 a = *(const float4*)(Ab + (long long)(m0 + mm) * lda + k0 + kq);
            As[kq + 0][mm] = a.x;
            As[kq + 1][mm] = a.y;
            As[kq + 2][mm] = a.z;
            As[kq + 3][mm] = a.w;
        }
        {
            int kk  = tid >> 4;
            int nn4 = (tid & 15) << 2;
            float4 b = *(const float4*)(Bb + (long long)(k0 + kk) * ldb + n0 + nn4);
            *(float4*)&Bs[kk][nn4] = b;
        }
        __syncthreads();

        #pragma unroll
        for (int kk = 0; kk < 16; kk++) {
            // 16B-aligned rows (68 floats = 17 x 16B): vector smem reads
            float4 ra = *(const float4*)&As[kk][ty * 4];
            float4 rb = *(const float4*)&Bs[kk][tx * 4];
            float va[4] = { ra.x, ra.y, ra.z, ra.w };
            float vb[4] = { rb.x, rb.y, rb.z, rb.w };
            #pragma unroll
            for (int i = 0; i < 4; i++)
                #pragma unroll
                for (int j = 0; j < 4; j++)
                    acc[i][j] = fmaf(va[i], vb[j], acc[i][j]);
        }
        __syncthreads();
    }

    #pragma unroll
    for (int i = 0; i < 4; i++)
        #pragma unroll
        for (int j = 0; j < 4; j++)
            Cb[(long long)(m0 + ty * 4 + i) * DIM + (n0 + tx * 4 + j)] = acc[i][j];
}

// ------------- reduce split-K partials -> bf16 hi/lo ------------------------
__global__ void reduce_split_kernel(const float* __restrict__ part,
                                    __nv_bfloat16* __restrict__ hi,
                                    __nv_bfloat16* __restrict__ lo)
{
    int idx = blockIdx.x * 256 + threadIdx.x;
    int h   = idx >> 16;
    int off = idx & 65535;
    const float* p = part + (long long)h * NSPLIT * 65536 + off;
    float acc = 0.f;
    #pragma unroll
    for (int s = 0; s < NSPLIT; s++) acc += p[(long long)s * 65536];
    __nv_bfloat16 hv = __float2bfloat16(acc);
    hi[idx] = hv;
    lo[idx] = __float2bfloat16(acc - __bfloat162float(hv));
}

// ---------------- row softmax (2048 cols) + bf16 hi/lo split ----------------
__global__ void softmax_split_kernel(const float* __restrict__ S,
                                     __nv_bfloat16* __restrict__ Phi,
                                     __nv_bfloat16* __restrict__ Plo)
{
    size_t row = blockIdx.x;
    const float* sr = S + row * (size_t)NTOK;
    int t = threadIdx.x;

    float v[8];
    float m = -1e30f;
    #pragma unroll
    for (int i = 0; i < 8; i++) {
        v[i] = sr[t + 256 * i];
        m = fmaxf(m, v[i]);
    }

    __shared__ float sred[8];
    float w = m;
    #pragma unroll
    for (int o = 16; o > 0; o >>= 1) w = fmaxf(w, __shfl_xor_sync(0xffffffffu, w, o));
    if ((t & 31) == 0) sred[t >> 5] = w;
    __syncthreads();
    if (t == 0) {
        float z = sred[0];
        #pragma unroll
        for (int i = 1; i < 8; i++) z = fmaxf(z, sred[i]);
        sred[0] = z;
    }
    __syncthreads();
    m = sred[0];
    __syncthreads();

    float sum = 0.f;
    #pragma unroll
    for (int i = 0; i < 8; i++) {
        v[i] = __expf(v[i] - m);
        sum += v[i];
    }
    float w2 = sum;
    #pragma unroll
    for (int o = 16; o > 0; o >>= 1) w2 += __shfl_xor_sync(0xffffffffu, w2, o);
    if ((t & 31) == 0) sred[t >> 5] = w2;
    __syncthreads();
    if (t == 0) {
        float z = 0.f;
        #pragma unroll
        for (int i = 0; i < 8; i++) z += sred[i];
        sred[0] = z;
    }
    __syncthreads();
    float inv = 1.0f / sred[0];

    size_t base = row * (size_t)NTOK;
    #pragma unroll
    for (int i = 0; i < 8; i++) {
        float p = v[i] * inv;
        __nv_bfloat16 h = __float2bfloat16(p);
        Phi[base + t + 256 * i] = h;
        Plo[base + t + 256 * i] = __float2bfloat16(p - __bfloat162float(h));
    }
}

// ---------------- reduce per-head partials ----------------------------------
__global__ void reduce_kernel(const float* __restrict__ op, float* __restrict__ out)
{
    int row = blockIdx.x;
    int t   = threadIdx.x;
    int b   = row >> 11;
    int q   = row & 2047;
    const float* base = op + (((long long)b * HEADS) * NTOK + q) * DIM + t;
    float acc = 0.f;
    #pragma unroll
    for (int h = 0; h < HEADS; h++)
        acc += base[(long long)h * NTOK * DIM];
    out[(long long)row * DIM + t] = acc;
}

// ---------------- launch ----------------------------------------------------
extern "C" void kernel_launch(void* const* d_in, const int* in_sizes, int n_in,
                              void* d_out, int out_size)
{
    const float* x     = (const float*)d_in[0];
    const float* gamma = (const float*)d_in[1];
    const float* Wq    = (const float*)d_in[2];
    const float* Wk    = (const float*)d_in[3];
    const float* Wv    = (const float*)d_in[4];
    const float* Wo    = (const float*)d_in[5];
    float* out = (float*)d_out;

    cudaFuncSetAttribute(mma_nt, cudaFuncAttributeMaxDynamicSharedMemorySize, MM_SMEM);

    float *xn, *pm, *pg, *tt, *ut, *s, *op;
    __nv_bfloat16 *xnh, *xnl, *mth, *mtl, *ghh, *ghl, *th, *tl, *uth, *utl, *ph, *pl;
    cudaGetSymbolAddress((void**)&xn,  g_xn);
    cudaGetSymbolAddress((void**)&pm,  g_pm);
    cudaGetSymbolAddress((void**)&pg,  g_pg);
    cudaGetSymbolAddress((void**)&tt,  g_t);
    cudaGetSymbolAddress((void**)&ut,  g_ut);
    cudaGetSymbolAddress((void**)&s,   g_s);
    cudaGetSymbolAddress((void**)&op,  g_op);
    cudaGetSymbolAddress((void**)&xnh, g_xnh);
    cudaGetSymbolAddress((void**)&xnl, g_xnl);
    cudaGetSymbolAddress((void**)&mth, g_mth);
    cudaGetSymbolAddress((void**)&mtl, g_mtl);
    cudaGetSymbolAddress((void**)&ghh, g_gh_);
    cudaGetSymbolAddress((void**)&ghl, g_gl_);
    cudaGetSymbolAddress((void**)&th,  g_th);
    cudaGetSymbolAddress((void**)&tl,  g_tl);
    cudaGetSymbolAddress((void**)&uth, g_uth);
    cudaGetSymbolAddress((void**)&utl, g_utl);
    cudaGetSymbolAddress((void**)&ph,  g_ph);
    cudaGetSymbolAddress((void**)&pl,  g_pl);

    const long long TD  = (long long)NTOK * DIM;
    const long long HTD = (long long)HEADS * TD;
    const long long SB  = (long long)NTOK * INNER;
    const long long DD  = (long long)DIM * DIM;

    // 1) LayerNorm + split
    ln_kernel<<<TOK, 256>>>(x, gamma, xn);
    split_kernel<<<(TOK * DIM / 4 + 255) / 256, 256>>>(xn, xnh, xnl, TOK * DIM / 4);

    // 2) precomputes (split-K): Mt_h = Wk_h^T Wq_h ; G_h = Wo_h Wv_h
    {
        dim3 grid(4, 4, HEADS * NSPLIT);
        gemm64_sk<true ><<<grid, 256>>>(Wk, Wq, pm, DIM, DIM);
        gemm64_sk<false><<<grid, 256>>>(Wo, Wv, pg, INNER, DIM);
        reduce_split_kernel<<<HEADS * DIM * DIM / 256, 256>>>(pm, mth, mtl);
        reduce_split_kernel<<<HEADS * DIM * DIM / 256, 256>>>(pg, ghh, ghl);
    }

    // 3) T[b][h] = xn_b * Mt_h^T  (NT), then split
    {
        dim3 grid(DIM / 128, NTOK / 128, BATCH * HEADS);
        mma_nt<<<grid, 256, MM_SMEM>>>(
            xnh, xnl, mth, mtl, tt,
            DIM, DIM, DIM, DIM, HEADS,
            TD, 0, 0, DD, HTD, TD, 1.0f);
    }
    split_kernel<<<(int)((BATCH * HTD / 4 + 255) / 256), 256>>>(tt, th, tl, BATCH * HTD / 4);

    // 4) S = scale * T * xn^T  (NT)
    {
        dim3 grid(NTOK / 128, NTOK / 128, BATCH * HEADS);
        mma_nt<<<grid, 256, MM_SMEM>>>(
            th, tl, xnh, xnl, s,
            DIM, DIM, DIM, INNER, HEADS,
            HTD, TD, TD, 0, SB, (long long)DHEAD,
            ATT_SCALE);
    }

    // 5) softmax + P split
    softmax_split_kernel<<<BATCH * NTOK * HEADS, 256>>>(s, ph, pl);

    // 6) Ut[b][h] = G_h * xn_b^T  (NT), then split
    {
        dim3 grid(NTOK / 128, DIM / 128, BATCH * HEADS);
        mma_nt<<<grid, 256, MM_SMEM>>>(
            ghh, ghl, xnh, xnl, ut,
            DIM, DIM, DIM, NTOK, HEADS,
            0, DD, TD, 0, HTD, TD, 1.0f);
    }
    split_kernel<<<(int)((BATCH * HTD / 4 + 255) / 256), 256>>>(ut, uth, utl, BATCH * HTD / 4);

    // 7) op[b][h] = P[b][h] * Ut[b][h]^T  (NT)
    {
        dim3 grid(DIM / 128, NTOK / 128, BATCH * HEADS);
        mma_nt<<<grid, 256, MM_SMEM>>>(
            ph, pl, uth, utl, op,
            NTOK, INNER, NTOK, DIM, HEADS,
            SB, (long long)DHEAD, HTD, TD, HTD, TD,
            1.0f);
    }

    // 8) out = sum_h op[b][h]
    reduce_kernel<<<TOK, 256>>>(op, out);
}

// round 11
// speedup vs baseline: 1.3727x; 1.0172x over previous
#include <cuda_runtime.h>
#include <cuda_bf16.h>
#include <math.h>
#include <stdint.h>

// Problem constants (confirmed: inner = DIM_HEAD*dim = 16384)
#define BATCH   2
#define NTOK    2048
#define DIM     256
#define HEADS   8
#define INNER   16384
#define DHEAD   2048
#define TOK     (BATCH*NTOK)      // 4096
#define ATT_SCALE 0.125f
#define LN_EPS  1e-5f
#define NSPLIT  8
#define KS      (DHEAD/NSPLIT)    // 256

// ---------------- scratch ---------------------------------------------------
__device__ float g_xn[TOK * DIM];
__device__ float g_pm[(size_t)HEADS * NSPLIT * DIM * DIM];
__device__ float g_pg[(size_t)HEADS * NSPLIT * DIM * DIM];
__device__ float g_s [(size_t)BATCH * NTOK * INNER];
__device__ float g_op[(size_t)BATCH * HEADS * NTOK * DIM];

__device__ __nv_bfloat16 g_xnh[TOK * DIM];
__device__ __nv_bfloat16 g_xnl[TOK * DIM];
__device__ __nv_bfloat16 g_mth[HEADS * DIM * DIM];
__device__ __nv_bfloat16 g_mtl[HEADS * DIM * DIM];
__device__ __nv_bfloat16 g_gh_[HEADS * DIM * DIM];
__device__ __nv_bfloat16 g_gl_[HEADS * DIM * DIM];
__device__ __nv_bfloat16 g_th [(size_t)BATCH * HEADS * NTOK * DIM];
__device__ __nv_bfloat16 g_tl [(size_t)BATCH * HEADS * NTOK * DIM];
__device__ __nv_bfloat16 g_uth[(size_t)BATCH * HEADS * DIM * NTOK];
__device__ __nv_bfloat16 g_utl[(size_t)BATCH * HEADS * DIM * NTOK];
__device__ __nv_bfloat16 g_ph [(size_t)BATCH * NTOK * INNER];
__device__ __nv_bfloat16 g_pl [(size_t)BATCH * NTOK * INNER];

// ---------------- asm helpers ------------------------------------------------
__device__ __forceinline__ uint32_t smem_u32(const void* p) {
    uint32_t a;
    asm("{ .reg .u64 tmp; cvta.to.shared.u64 tmp, %1; cvt.u32.u64 %0, tmp; }"
        : "=r"(a) : "l"(p));
    return a;
}
__device__ __forceinline__ void ldsm4u(uint32_t* d, uint32_t a)
{
    asm volatile("ldmatrix.sync.aligned.m8n8.x4.shared.b16 {%0,%1,%2,%3}, [%4];"
                 : "=r"(d[0]), "=r"(d[1]), "=r"(d[2]), "=r"(d[3]) : "r"(a));
}
__device__ __forceinline__ void mma_bf16(float* d, const uint32_t* a, const uint32_t* b)
{
    asm volatile(
        "mma.sync.aligned.m16n8k16.row.col.f32.bf16.bf16.f32 "
        "{%0,%1,%2,%3}, {%4,%5,%6,%7}, {%8,%9}, {%0,%1,%2,%3};"
        : "+f"(d[0]), "+f"(d[1]), "+f"(d[2]), "+f"(d[3])
        : "r"(a[0]), "r"(a[1]), "r"(a[2]), "r"(a[3]), "r"(b[0]), "r"(b[1]));
}
#define CP16(dst, src) \
    asm volatile("cp.async.cg.shared.global [%0], [%1], 16;" :: "r"(dst), "l"(src))
#define CP_COMMIT() asm volatile("cp.async.commit_group;" ::: "memory")
#define CP_WAIT0()  asm volatile("cp.async.wait_group 0;" ::: "memory")

// stage layout (bytes): 4 tiles of 128 rows x 40 bf16 (80B rows)
#define OFF_AH  0
#define OFF_AL  10240
#define OFF_BH  20480
#define OFF_BL  30720
#define STAGE   40960
#define MM_SMEM (2 * STAGE)

// ---------------- bf16 split tensor-core GEMM (NT), single-sync pipeline ----
// C[m][n] = alpha * sum_k (Ahi*Bhi + Ahi*Blo + Alo*Bhi)[m][k][n]
// SPLIT_OUT=false: write fp32 C.  SPLIT_OUT=true: write bf16 hi/lo pair.
// A row-major (M,K), B row-major (N,K). Block 128x128, 8 warps of 32x64, k32 chunks.
template<bool SPLIT_OUT>
__global__ void __launch_bounds__(256, 2)
mma_nt(const __nv_bfloat16* __restrict__ Ahi, const __nv_bfloat16* __restrict__ Alo,
       const __nv_bfloat16* __restrict__ Bhi, const __nv_bfloat16* __restrict__ Blo,
       float* __restrict__ C,
       __nv_bfloat16* __restrict__ Chi, __nv_bfloat16* __restrict__ Clo,
       int K, int lda, int ldb, int ldc,
       int hdiv,
       long long sAb, long long sAh,
       long long sBb, long long sBh,
       long long sCb, long long sCh,
       float alpha)
{
    extern __shared__ __align__(16) char smem[];
    uint32_t sb = smem_u32(smem);

    int bz = blockIdx.z;
    int zb = bz / hdiv, zh = bz % hdiv;
    long long aoff = (long long)zb * sAb + (long long)zh * sAh;
    long long boff = (long long)zb * sBb + (long long)zh * sBh;
    long long coff = (long long)zb * sCb + (long long)zh * sCh;
    const __nv_bfloat16* Ah = Ahi + aoff;
    const __nv_bfloat16* Al = Alo + aoff;
    const __nv_bfloat16* Bh = Bhi + boff;
    const __nv_bfloat16* Bl = Blo + boff;

    int m0 = blockIdx.y * 128;
    int n0 = blockIdx.x * 128;
    int tid  = threadIdx.x;
    int warp = tid >> 5;
    int lane = tid & 31;
    int wm = (warp & 3) * 32;
    int wn = (warp >> 2) * 64;

    int r  = tid >> 2;            // 0..63 (rows r and r+64)
    int kc = (tid & 3) * 8;       // k element offset (16B)

    float acc[2][8][4];
    #pragma unroll
    for (int i = 0; i < 2; i++)
        #pragma unroll
        for (int j = 0; j < 8; j++)
            #pragma unroll
            for (int c = 0; c < 4; c++) acc[i][j][c] = 0.f;

    const int NC = K / 32;

    auto load_stage = [&](int st, int k0) {
        uint32_t s0 = sb + (uint32_t)st * STAGE;
        #pragma unroll
        for (int i = 0; i < 2; i++) {
            int row = r + i * 64;
            uint32_t so = (uint32_t)row * 80 + (uint32_t)kc * 2;
            CP16(s0 + OFF_AH + so, Ah + (long long)(m0 + row) * lda + k0 + kc);
            CP16(s0 + OFF_AL + so, Al + (long long)(m0 + row) * lda + k0 + kc);
            CP16(s0 + OFF_BH + so, Bh + (long long)(n0 + row) * ldb + k0 + kc);
            CP16(s0 + OFF_BL + so, Bl + (long long)(n0 + row) * ldb + k0 + kc);
        }
    };

    load_stage(0, 0);
    CP_COMMIT();

    for (int i = 0; i < NC; i++) {
        // stage i is the only outstanding group
        CP_WAIT0();
        __syncthreads();          // also proves compute(i-1) done -> buffer (i+1)&1 reusable
        if (i + 1 < NC) { load_stage((i + 1) & 1, (i + 1) * 32); CP_COMMIT(); }

        uint32_t base = sb + (uint32_t)(i & 1) * STAGE;

        #pragma unroll
        for (int s = 0; s < 32; s += 16) {
            uint32_t ah[2][4], al[2][4];
            #pragma unroll
            for (int ii = 0; ii < 2; ii++) {
                uint32_t ra = base + (uint32_t)(wm + ii * 16 + (lane & 15)) * 80
                            + (uint32_t)(s + ((lane >> 4) << 3)) * 2;
                ldsm4u(ah[ii], ra + OFF_AH);
                ldsm4u(al[ii], ra + OFF_AL);
            }
            #pragma unroll
            for (int j = 0; j < 4; j++) {
                uint32_t rb = base + (uint32_t)(wn + j * 16 + ((lane >> 4) << 3) + (lane & 7)) * 80
                            + (uint32_t)(s + ((lane >> 3) & 1) * 8) * 2;
                uint32_t bh[4], bl[4];
                ldsm4u(bh, rb + OFF_BH);
                ldsm4u(bl, rb + OFF_BL);
                #pragma unroll
                for (int jj = 0; jj < 2; jj++) {
                    #pragma unroll
                    for (int ii = 0; ii < 2; ii++) {
                        mma_bf16(acc[ii][j * 2 + jj], ah[ii], bh + jj * 2);
                        mma_bf16(acc[ii][j * 2 + jj], ah[ii], bl + jj * 2);
                        mma_bf16(acc[ii][j * 2 + jj], al[ii], bh + jj * 2);
                    }
                }
            }
        }
    }

    // epilogue (registers -> gmem; no smem dependency, no trailing sync needed)
    #pragma unroll
    for (int i = 0; i < 2; i++) {
        #pragma unroll
        for (int j = 0; j < 8; j++) {
            int row = m0 + wm + i * 16 + (lane >> 2);
            int col = n0 + wn + j * 8 + (lane & 3) * 2;
            #pragma unroll
            for (int hh = 0; hh < 2; hh++) {
                long long off = coff + (long long)(row + hh * 8) * ldc + col;
                float v0 = alpha * acc[i][j][hh * 2 + 0];
                float v1 = alpha * acc[i][j][hh * 2 + 1];
                if (SPLIT_OUT) {
                    __nv_bfloat16 h0 = __float2bfloat16(v0);
                    __nv_bfloat16 h1 = __float2bfloat16(v1);
                    __nv_bfloat16 l0 = __float2bfloat16(v0 - __bfloat162float(h0));
                    __nv_bfloat16 l1 = __float2bfloat16(v1 - __bfloat162float(h1));
                    *(__nv_bfloat162*)(Chi + off) = __nv_bfloat162{h0, h1};
                    *(__nv_bfloat162*)(Clo + off) = __nv_bfloat162{l0, l1};
                } else {
                    float2 v = { v0, v1 };
                    *(float2*)(C + off) = v;
                }
            }
        }
    }
}

// ---------------- LayerNorm -------------------------------------------------
__global__ void ln_kernel(const float* __restrict__ x,
                          const float* __restrict__ gamma,
                          float* __restrict__ xn)
{
    int row = blockIdx.x;
    int t   = threadIdx.x;
    float v = x[row * DIM + t];

    __shared__ float s1[8], s2[8];
    float a = v, b = v * v;
    #pragma unroll
    for (int o = 16; o > 0; o >>= 1) {
        a += __shfl_xor_sync(0xffffffffu, a, o);
        b += __shfl_xor_sync(0xffffffffu, b, o);
    }
    int lane = t & 31, w = t >> 5;
    if (lane == 0) { s1[w] = a; s2[w] = b; }
    __syncthreads();
    if (t == 0) {
        float sa = 0.f, sb = 0.f;
        #pragma unroll
        for (int i = 0; i < 8; i++) { sa += s1[i]; sb += s2[i]; }
        s1[0] = sa * (1.0f / DIM);
        s2[0] = sb * (1.0f / DIM);
    }
    __syncthreads();
    float mu  = s1[0];
    float var = s2[0] - mu * mu;
    float rr  = rsqrtf(var + LN_EPS);
    xn[row * DIM + t] = (v - mu) * rr * (gamma[t] + 1.0f);
}

// ---------------- fp32 -> bf16 hi/lo split (xn only) -------------------------
__global__ void split_kernel(const float* __restrict__ src,
                             __nv_bfloat16* __restrict__ hi,
                             __nv_bfloat16* __restrict__ lo,
                             long long n4)
{
    long long i = ((long long)blockIdx.x * blockDim.x + threadIdx.x);
    if (i >= n4) return;
    long long e = i * 4;
    float4 v = *(const float4*)(src + e);
    __nv_bfloat16 h0 = __float2bfloat16(v.x);
    __nv_bfloat16 h1 = __float2bfloat16(v.y);
    __nv_bfloat16 h2 = __float2bfloat16(v.z);
    __nv_bfloat16 h3 = __float2bfloat16(v.w);
    __nv_bfloat16 l0 = __float2bfloat16(v.x - __bfloat162float(h0));
    __nv_bfloat16 l1 = __float2bfloat16(v.y - __bfloat162float(h1));
    __nv_bfloat16 l2 = __float2bfloat16(v.z - __bfloat162float(h2));
    __nv_bfloat16 l3 = __float2bfloat16(v.w - __bfloat162float(h3));
    ((__nv_bfloat162*)(hi + e))[0] = __nv_bfloat162{h0, h1};
    ((__nv_bfloat162*)(hi + e))[1] = __nv_bfloat162{h2, h3};
    ((__nv_bfloat162*)(lo + e))[0] = __nv_bfloat162{l0, l1};
    ((__nv_bfloat162*)(lo + e))[1] = __nv_bfloat162{l2, l3};
}

// ---------------- split-K 64x64 GEMM for head precomputes --------------------
template<bool AT>
__global__ void __launch_bounds__(256)
gemm64_sk(const float* __restrict__ A, const float* __restrict__ B,
          float* __restrict__ Cp, int lda, int ldb)
{
    __shared__ float As[16][68];
    __shared__ float Bs[16][68];

    int z = blockIdx.z;
    int h = z / NSPLIT, sp = z % NSPLIT;
    long long hk0 = (long long)h * DHEAD + (long long)sp * KS;

    const float* Ab = AT ? (A + hk0 * lda) : (A + hk0);
    const float* Bb = B + hk0 * ldb;
    float* Cb = Cp + (long long)z * DIM * DIM;

    int m0 = blockIdx.y * 64;
    int n0 = blockIdx.x * 64;
    int tid = threadIdx.x;
    int tx = tid & 15;
    int ty = tid >> 4;

    float acc[4][4];
    #pragma unroll
    for (int i = 0; i < 4; i++)
        #pragma unroll
        for (int j = 0; j < 4; j++) acc[i][j] = 0.f;

    for (int k0 = 0; k0 < KS; k0 += 16) {
        if (AT) {
            int kk  = tid >> 4;
            int mm4 = (tid & 15) << 2;
            float4 a = *(const float4*)(Ab + (long long)(k0 + kk) * lda + m0 + mm4);
            *(float4*)&As[kk][mm4] = a;
        } else {
            int mm = tid >> 2;
            int kq = (tid & 3) << 2;
            float4 a = *(const float4*)(Ab + (long long)(m0 + mm) * lda + k0 + kq);
            As[kq + 0][mm] = a.x;
            As[kq + 1][mm] = a.y;
            As[kq + 2][mm] = a.z;
            As[kq + 3][mm] = a.w;
        }
        {
            int kk  = tid >> 4;
            int nn4 = (tid & 15) << 2;
            float4 b = *(const float4*)(Bb + (long long)(k0 + kk) * ldb + n0 + nn4);
            *(float4*)&Bs[kk][nn4] = b;
        }
        __syncthreads();

        #pragma unroll
        for (int kk = 0; kk < 16; kk++) {
            float4 ra = *(const float4*)&As[kk][ty * 4];
            float4 rb = *(const float4*)&Bs[kk][tx * 4];
            float va[4] = { ra.x, ra.y, ra.z, ra.w };
            float vb[4] = { rb.x, rb.y, rb.z, rb.w };
            #pragma unroll
            for (int i = 0; i < 4; i++)
                #pragma unroll
                for (int j = 0; j < 4; j++)
                    acc[i][j] = fmaf(va[i], vb[j], acc[i][j]);
        }
        __syncthreads();
    }

    #pragma unroll
    for (int i = 0; i < 4; i++)
        #pragma unroll
        for (int j = 0; j < 4; j++)
            Cb[(long long)(m0 + ty * 4 + i) * DIM + (n0 + tx * 4 + j)] = acc[i][j];
}

// ------------- reduce split-K partials -> bf16 hi/lo ------------------------
__global__ void reduce_split_kernel(const float* __restrict__ part,
                                    __nv_bfloat16* __restrict__ hi,
                                    __nv_bfloat16* __restrict__ lo)
{
    int idx = blockIdx.x * 256 + threadIdx.x;
    int h   = idx >> 16;
    int off = idx & 65535;
    const float* p = part + (long long)h * NSPLIT * 65536 + off;
    float acc = 0.f;
    #pragma unroll
    for (int s = 0; s < NSPLIT; s++) acc += p[(long long)s * 65536];
    __nv_bfloat16 hv = __float2bfloat16(acc);
    hi[idx] = hv;
    lo[idx] = __float2bfloat16(acc - __bfloat162float(hv));
}

// ---------------- row softmax (2048 cols) + bf16 hi/lo split ----------------
__global__ void softmax_split_kernel(const float* __restrict__ S,
                                     __nv_bfloat16* __restrict__ Phi,
                                     __nv_bfloat16* __restrict__ Plo)
{
    size_t row = blockIdx.x;
    const float* sr = S + row * (size_t)NTOK;
    int t = threadIdx.x;

    float v[8];
    float m = -1e30f;
    #pragma unroll
    for (int i = 0; i < 8; i++) {
        v[i] = sr[t + 256 * i];
        m = fmaxf(m, v[i]);
    }

    __shared__ float sred[8];
    float w = m;
    #pragma unroll
    for (int o = 16; o > 0; o >>= 1) w = fmaxf(w, __shfl_xor_sync(0xffffffffu, w, o));
    if ((t & 31) == 0) sred[t >> 5] = w;
    __syncthreads();
    if (t == 0) {
        float z = sred[0];
        #pragma unroll
        for (int i = 1; i < 8; i++) z = fmaxf(z, sred[i]);
        sred[0] = z;
    }
    __syncthreads();
    m = sred[0];
    __syncthreads();

    float sum = 0.f;
    #pragma unroll
    for (int i = 0; i < 8; i++) {
        v[i] = __expf(v[i] - m);
        sum += v[i];
    }
    float w2 = sum;
    #pragma unroll
    for (int o = 16; o > 0; o >>= 1) w2 += __shfl_xor_sync(0xffffffffu, w2, o);
    if ((t & 31) == 0) sred[t >> 5] = w2;
    __syncthreads();
    if (t == 0) {
        float z = 0.f;
        #pragma unroll
        for (int i = 0; i < 8; i++) z += sred[i];
        sred[0] = z;
    }
    __syncthreads();
    float inv = 1.0f / sred[0];

    size_t base = row * (size_t)NTOK;
    #pragma unroll
    for (int i = 0; i < 8; i++) {
        float p = v[i] * inv;
        __nv_bfloat16 h = __float2bfloat16(p);
        Phi[base + t + 256 * i] = h;
        Plo[base + t + 256 * i] = __float2bfloat16(p - __bfloat162float(h));
    }
}

// ---------------- reduce per-head partials ----------------------------------
__global__ void reduce_kernel(const float* __restrict__ op, float* __restrict__ out)
{
    int row = blockIdx.x;
    int t   = threadIdx.x;
    int b   = row >> 11;
    int q   = row & 2047;
    const float* base = op + (((long long)b * HEADS) * NTOK + q) * DIM + t;
    float acc = 0.f;
    #pragma unroll
    for (int h = 0; h < HEADS; h++)
        acc += base[(long long)h * NTOK * DIM];
    out[(long long)row * DIM + t] = acc;
}

// ---------------- launch ----------------------------------------------------
extern "C" void kernel_launch(void* const* d_in, const int* in_sizes, int n_in,
                              void* d_out, int out_size)
{
    const float* x     = (const float*)d_in[0];
    const float* gamma = (const float*)d_in[1];
    const float* Wq    = (const float*)d_in[2];
    const float* Wk    = (const float*)d_in[3];
    const float* Wv    = (const float*)d_in[4];
    const float* Wo    = (const float*)d_in[5];
    float* out = (float*)d_out;

    cudaFuncSetAttribute(mma_nt<false>, cudaFuncAttributeMaxDynamicSharedMemorySize, MM_SMEM);
    cudaFuncSetAttribute(mma_nt<true>,  cudaFuncAttributeMaxDynamicSharedMemorySize, MM_SMEM);

    float *xn, *pm, *pg, *s, *op;
    __nv_bfloat16 *xnh, *xnl, *mth, *mtl, *ghh, *ghl, *th, *tl, *uth, *utl, *ph, *pl;
    cudaGetSymbolAddress((void**)&xn,  g_xn);
    cudaGetSymbolAddress((void**)&pm,  g_pm);
    cudaGetSymbolAddress((void**)&pg,  g_pg);
    cudaGetSymbolAddress((void**)&s,   g_s);
    cudaGetSymbolAddress((void**)&op,  g_op);
    cudaGetSymbolAddress((void**)&xnh, g_xnh);
    cudaGetSymbolAddress((void**)&xnl, g_xnl);
    cudaGetSymbolAddress((void**)&mth, g_mth);
    cudaGetSymbolAddress((void**)&mtl, g_mtl);
    cudaGetSymbolAddress((void**)&ghh, g_gh_);
    cudaGetSymbolAddress((void**)&ghl, g_gl_);
    cudaGetSymbolAddress((void**)&th,  g_th);
    cudaGetSymbolAddress((void**)&tl,  g_tl);
    cudaGetSymbolAddress((void**)&uth, g_uth);
    cudaGetSymbolAddress((void**)&utl, g_utl);
    cudaGetSymbolAddress((void**)&ph,  g_ph);
    cudaGetSymbolAddress((void**)&pl,  g_pl);

    const long long TD  = (long long)NTOK * DIM;
    const long long HTD = (long long)HEADS * TD;
    const long long SB  = (long long)NTOK * INNER;
    const long long DD  = (long long)DIM * DIM;

    // 1) LayerNorm + split xn
    ln_kernel<<<TOK, 256>>>(x, gamma, xn);
    split_kernel<<<(TOK * DIM / 4 + 255) / 256, 256>>>(xn, xnh, xnl, TOK * DIM / 4);

    // 2) precomputes (split-K): Mt_h = Wk_h^T Wq_h ; G_h = Wo_h Wv_h
    {
        dim3 grid(4, 4, HEADS * NSPLIT);
        gemm64_sk<true ><<<grid, 256>>>(Wk, Wq, pm, DIM, DIM);
        gemm64_sk<false><<<grid, 256>>>(Wo, Wv, pg, INNER, DIM);
        reduce_split_kernel<<<HEADS * DIM * DIM / 256, 256>>>(pm, mth, mtl);
        reduce_split_kernel<<<HEADS * DIM * DIM / 256, 256>>>(pg, ghh, ghl);
    }

    // 3) T[b][h] = xn_b * Mt_h^T  (NT, split-out epilogue)
    {
        dim3 grid(DIM / 128, NTOK / 128, BATCH * HEADS);
        mma_nt<true><<<grid, 256, MM_SMEM>>>(
            xnh, xnl, mth, mtl, nullptr, th, tl,
            DIM, DIM, DIM, DIM, HEADS,
            TD, 0, 0, DD, HTD, TD, 1.0f);
    }

    // 4) S = scale * T * xn^T  (NT, fp32 out)
    {
        dim3 grid(NTOK / 128, NTOK / 128, BATCH * HEADS);
        mma_nt<false><<<grid, 256, MM_SMEM>>>(
            th, tl, xnh, xnl, s, nullptr, nullptr,
            DIM, DIM, DIM, INNER, HEADS,
            HTD, TD, TD, 0, SB, (long long)DHEAD,
            ATT_SCALE);
    }

    // 5) softmax + P split
    softmax_split_kernel<<<BATCH * NTOK * HEADS, 256>>>(s, ph, pl);

    // 6) Ut[b][h] = G_h * xn_b^T  (NT, split-out epilogue)
    {
        dim3 grid(NTOK / 128, DIM / 128, BATCH * HEADS);
        mma_nt<true><<<grid, 256, MM_SMEM>>>(
            ghh, ghl, xnh, xnl, nullptr, uth, utl,
            DIM, DIM, DIM, NTOK, HEADS,
            0, DD, TD, 0, HTD, TD, 1.0f);
    }

    // 7) op[b][h] = P[b][h] * Ut[b][h]^T  (NT, fp32 out)
    {
        dim3 grid(DIM / 128, NTOK / 128, BATCH * HEADS);
        mma_nt<false><<<grid, 256, MM_SMEM>>>(
            ph, pl, uth, utl, op, nullptr, nullptr,
            NTOK, INNER, NTOK, DIM, HEADS,
            SB, (long long)DHEAD, HTD, TD, HTD, TD,
            1.0f);
    }

    // 8) out = sum_h op[b][h]
    reduce_kernel<<<TOK, 256>>>(op, out);
}

// round 12
// speedup vs baseline: 1.4211x; 1.0353x over previous
#include <cuda_runtime.h>
#include <cuda_bf16.h>
#include <math.h>
#include <stdint.h>

// Problem constants (confirmed: inner = DIM_HEAD*dim = 16384)
#define BATCH   2
#define NTOK    2048
#define DIM     256
#define HEADS   8
#define INNER   16384
#define DHEAD   2048
#define TOK     (BATCH*NTOK)      // 4096
#define ATT_SCALE 0.125f
#define LN_EPS  1e-5f
#define NSPLIT  8
#define KS      (DHEAD/NSPLIT)    // 256
#define NTILES  (NTOK/128)        // 16 column tiles per head block
#define NROWS   (BATCH*HEADS*NTOK) // 32768 attention rows

// ---------------- scratch ---------------------------------------------------
__device__ float g_xn[TOK * DIM];
__device__ float g_pm[(size_t)HEADS * NSPLIT * DIM * DIM];
__device__ float g_pg[(size_t)HEADS * NSPLIT * DIM * DIM];
__device__ float g_op[(size_t)BATCH * HEADS * NTOK * DIM];
__device__ float g_sp[(size_t)NROWS * NTILES];   // row-sum partials
__device__ float g_ri[NROWS];                    // 1/rowsum

__device__ __nv_bfloat16 g_xnh[TOK * DIM];
__device__ __nv_bfloat16 g_xnl[TOK * DIM];
__device__ __nv_bfloat16 g_mth[HEADS * DIM * DIM];
__device__ __nv_bfloat16 g_mtl[HEADS * DIM * DIM];
__device__ __nv_bfloat16 g_gh_[HEADS * DIM * DIM];
__device__ __nv_bfloat16 g_gl_[HEADS * DIM * DIM];
__device__ __nv_bfloat16 g_th [(size_t)BATCH * HEADS * NTOK * DIM];
__device__ __nv_bfloat16 g_tl [(size_t)BATCH * HEADS * NTOK * DIM];
__device__ __nv_bfloat16 g_uth[(size_t)BATCH * HEADS * DIM * NTOK];
__device__ __nv_bfloat16 g_utl[(size_t)BATCH * HEADS * DIM * NTOK];
__device__ __nv_bfloat16 g_eh [(size_t)BATCH * NTOK * INNER];   // exp(logits) hi
__device__ __nv_bfloat16 g_el [(size_t)BATCH * NTOK * INNER];   // exp(logits) lo

// ---------------- asm helpers ------------------------------------------------
__device__ __forceinline__ uint32_t smem_u32(const void* p) {
    uint32_t a;
    asm("{ .reg .u64 tmp; cvta.to.shared.u64 tmp, %1; cvt.u32.u64 %0, tmp; }"
        : "=r"(a) : "l"(p));
    return a;
}
__device__ __forceinline__ void ldsm4u(uint32_t* d, uint32_t a)
{
    asm volatile("ldmatrix.sync.aligned.m8n8.x4.shared.b16 {%0,%1,%2,%3}, [%4];"
                 : "=r"(d[0]), "=r"(d[1]), "=r"(d[2]), "=r"(d[3]) : "r"(a));
}
__device__ __forceinline__ void mma_bf16(float* d, const uint32_t* a, const uint32_t* b)
{
    asm volatile(
        "mma.sync.aligned.m16n8k16.row.col.f32.bf16.bf16.f32 "
        "{%0,%1,%2,%3}, {%4,%5,%6,%7}, {%8,%9}, {%0,%1,%2,%3};"
        : "+f"(d[0]), "+f"(d[1]), "+f"(d[2]), "+f"(d[3])
        : "r"(a[0]), "r"(a[1]), "r"(a[2]), "r"(a[3]), "r"(b[0]), "r"(b[1]));
}
#define CP16(dst, src) \
    asm volatile("cp.async.cg.shared.global [%0], [%1], 16;" :: "r"(dst), "l"(src))
#define CP_COMMIT() asm volatile("cp.async.commit_group;" ::: "memory")
#define CP_WAIT0()  asm volatile("cp.async.wait_group 0;" ::: "memory")

// stage layout (bytes): 4 tiles of 128 rows x 40 bf16 (80B rows)
#define OFF_AH  0
#define OFF_AL  10240
#define OFF_BH  20480
#define OFF_BL  30720
#define STAGE   40960
#define MM_SMEM (2 * STAGE)

// mma_nt output modes
#define OUT_F32   0   // C = alpha * acc                (fp32)
#define OUT_SPLIT 1   // Chi/Clo = bf16 hi/lo of acc    (alpha applied)
#define OUT_EXP   2   // Chi/Clo = bf16 hi/lo of exp(alpha*acc), + row-sum partials
#define OUT_DIV   3   // C = rinv[row] * acc            (fp32)

// ---------------- bf16 split tensor-core GEMM (NT), single-sync pipeline ----
// acc[m][n] = sum_k (Ahi*Bhi + Ahi*Blo + Alo*Bhi)
// A row-major (M,K), B row-major (N,K). Block 128x128, 8 warps of 32x64, k32 chunks.
template<int MODE>
__global__ void __launch_bounds__(256, 2)
mma_nt(const __nv_bfloat16* __restrict__ Ahi, const __nv_bfloat16* __restrict__ Alo,
       const __nv_bfloat16* __restrict__ Bhi, const __nv_bfloat16* __restrict__ Blo,
       float* __restrict__ C,
       __nv_bfloat16* __restrict__ Chi, __nv_bfloat16* __restrict__ Clo,
       float* __restrict__ Part, const float* __restrict__ Rinv,
       int K, int lda, int ldb, int ldc,
       int hdiv,
       long long sAb, long long sAh,
       long long sBb, long long sBh,
       long long sCb, long long sCh,
       float alpha)
{
    extern __shared__ __align__(16) char smem[];
    __shared__ float ssum[128][2];
    uint32_t sb = smem_u32(smem);

    int bz = blockIdx.z;
    int zb = bz / hdiv, zh = bz % hdiv;
    long long aoff = (long long)zb * sAb + (long long)zh * sAh;
    long long boff = (long long)zb * sBb + (long long)zh * sBh;
    long long coff = (long long)zb * sCb + (long long)zh * sCh;
    const __nv_bfloat16* Ah = Ahi + aoff;
    const __nv_bfloat16* Al = Alo + aoff;
    const __nv_bfloat16* Bh = Bhi + boff;
    const __nv_bfloat16* Bl = Blo + boff;

    int m0 = blockIdx.y * 128;
    int n0 = blockIdx.x * 128;
    int tid  = threadIdx.x;
    int warp = tid >> 5;
    int lane = tid & 31;
    int wm = (warp & 3) * 32;
    int wn = (warp >> 2) * 64;

    int r  = tid >> 2;            // 0..63 (rows r and r+64)
    int kc = (tid & 3) * 8;       // k element offset (16B)

    float acc[2][8][4];
    #pragma unroll
    for (int i = 0; i < 2; i++)
        #pragma unroll
        for (int j = 0; j < 8; j++)
            #pragma unroll
            for (int c = 0; c < 4; c++) acc[i][j][c] = 0.f;

    const int NC = K / 32;

    auto load_stage = [&](int st, int k0) {
        uint32_t s0 = sb + (uint32_t)st * STAGE;
        #pragma unroll
        for (int i = 0; i < 2; i++) {
            int row = r + i * 64;
            uint32_t so = (uint32_t)row * 80 + (uint32_t)kc * 2;
            CP16(s0 + OFF_AH + so, Ah + (long long)(m0 + row) * lda + k0 + kc);
            CP16(s0 + OFF_AL + so, Al + (long long)(m0 + row) * lda + k0 + kc);
            CP16(s0 + OFF_BH + so, Bh + (long long)(n0 + row) * ldb + k0 + kc);
            CP16(s0 + OFF_BL + so, Bl + (long long)(n0 + row) * ldb + k0 + kc);
        }
    };

    load_stage(0, 0);
    CP_COMMIT();

    for (int i = 0; i < NC; i++) {
        CP_WAIT0();
        __syncthreads();          // also proves compute(i-1) done -> buffer (i+1)&1 reusable
        if (i + 1 < NC) { load_stage((i + 1) & 1, (i + 1) * 32); CP_COMMIT(); }

        uint32_t base = sb + (uint32_t)(i & 1) * STAGE;

        #pragma unroll
        for (int s = 0; s < 32; s += 16) {
            uint32_t ah[2][4], al[2][4];
            #pragma unroll
            for (int ii = 0; ii < 2; ii++) {
                uint32_t ra = base + (uint32_t)(wm + ii * 16 + (lane & 15)) * 80
                            + (uint32_t)(s + ((lane >> 4) << 3)) * 2;
                ldsm4u(ah[ii], ra + OFF_AH);
                ldsm4u(al[ii], ra + OFF_AL);
            }
            #pragma unroll
            for (int j = 0; j < 4; j++) {
                uint32_t rb = base + (uint32_t)(wn + j * 16 + ((lane >> 4) << 3) + (lane & 7)) * 80
                            + (uint32_t)(s + ((lane >> 3) & 1) * 8) * 2;
                uint32_t bh[4], bl[4];
                ldsm4u(bh, rb + OFF_BH);
                ldsm4u(bl, rb + OFF_BL);
                #pragma unroll
                for (int jj = 0; jj < 2; jj++) {
                    #pragma unroll
                    for (int ii = 0; ii < 2; ii++) {
                        mma_bf16(acc[ii][j * 2 + jj], ah[ii], bh + jj * 2);
                        mma_bf16(acc[ii][j * 2 + jj], ah[ii], bl + jj * 2);
                        mma_bf16(acc[ii][j * 2 + jj], al[ii], bh + jj * 2);
                    }
                }
            }
        }
    }

    // ---------------- epilogue ----------------
    float rowacc[2][2] = {{0.f, 0.f}, {0.f, 0.f}};   // (i, hh) row sums (OUT_EXP)
    float rv[2][2];                                   // rinv per (i, hh) row (OUT_DIV)
    if (MODE == OUT_DIV) {
        #pragma unroll
        for (int i = 0; i < 2; i++)
            #pragma unroll
            for (int hh = 0; hh < 2; hh++)
                rv[i][hh] = Rinv[(long long)bz * NTOK + m0 + wm + i * 16 + hh * 8 + (lane >> 2)];
    }

    #pragma unroll
    for (int i = 0; i < 2; i++) {
        #pragma unroll
        for (int j = 0; j < 8; j++) {
            int row = m0 + wm + i * 16 + (lane >> 2);
            int col = n0 + wn + j * 8 + (lane & 3) * 2;
            #pragma unroll
            for (int hh = 0; hh < 2; hh++) {
                long long off = coff + (long long)(row + hh * 8) * ldc + col;
                float v0 = acc[i][j][hh * 2 + 0];
                float v1 = acc[i][j][hh * 2 + 1];
                if (MODE == OUT_F32) {
                    float2 v = { alpha * v0, alpha * v1 };
                    *(float2*)(C + off) = v;
                } else if (MODE == OUT_SPLIT) {
                    v0 *= alpha; v1 *= alpha;
                    __nv_bfloat16 h0 = __float2bfloat16(v0);
                    __nv_bfloat16 h1 = __float2bfloat16(v1);
                    __nv_bfloat16 l0 = __float2bfloat16(v0 - __bfloat162float(h0));
                    __nv_bfloat16 l1 = __float2bfloat16(v1 - __bfloat162float(h1));
                    *(__nv_bfloat162*)(Chi + off) = __nv_bfloat162{h0, h1};
                    *(__nv_bfloat162*)(Clo + off) = __nv_bfloat162{l0, l1};
                } else if (MODE == OUT_EXP) {
                    float e0 = __expf(alpha * v0);
                    float e1 = __expf(alpha * v1);
                    __nv_bfloat16 h0 = __float2bfloat16(e0);
                    __nv_bfloat16 h1 = __float2bfloat16(e1);
                    __nv_bfloat16 l0 = __float2bfloat16(e0 - __bfloat162float(h0));
                    __nv_bfloat16 l1 = __float2bfloat16(e1 - __bfloat162float(h1));
                    *(__nv_bfloat162*)(Chi + off) = __nv_bfloat162{h0, h1};
                    *(__nv_bfloat162*)(Clo + off) = __nv_bfloat162{l0, l1};
                    rowacc[i][hh] += e0 + e1;
                } else { // OUT_DIV
                    float2 v = { rv[i][hh] * v0, rv[i][hh] * v1 };
                    *(float2*)(C + off) = v;
                }
            }
        }
    }

    if (MODE == OUT_EXP) {
        // reduce across the quad (lanes sharing lane>>2), then across wn halves
        #pragma unroll
        for (int i = 0; i < 2; i++)
            #pragma unroll
            for (int hh = 0; hh < 2; hh++) {
                rowacc[i][hh] += __shfl_xor_sync(0xffffffffu, rowacc[i][hh], 1);
                rowacc[i][hh] += __shfl_xor_sync(0xffffffffu, rowacc[i][hh], 2);
            }
        if ((lane & 3) == 0) {
            #pragma unroll
            for (int i = 0; i < 2; i++)
                #pragma unroll
                for (int hh = 0; hh < 2; hh++)
                    ssum[wm + i * 16 + hh * 8 + (lane >> 2)][warp >> 2] = rowacc[i][hh];
        }
        __syncthreads();
        if (tid < 128) {
            float sp = ssum[tid][0] + ssum[tid][1];
            Part[((long long)bz * NTOK + m0 + tid) * NTILES + blockIdx.x] = sp;
        }
    }
}

// ---------------- rowsum -> reciprocal ---------------------------------------
__global__ void rowsum_kernel(const float* __restrict__ part, float* __restrict__ rinv)
{
    int idx = blockIdx.x * 256 + threadIdx.x;     // 0 .. NROWS-1
    const float* p = part + (long long)idx * NTILES;
    float s = 0.f;
    #pragma unroll
    for (int i = 0; i < NTILES; i++) s += p[i];
    rinv[idx] = 1.0f / s;
}

// ---------------- LayerNorm -------------------------------------------------
__global__ void ln_kernel(const float* __restrict__ x,
                          const float* __restrict__ gamma,
                          float* __restrict__ xn)
{
    int row = blockIdx.x;
    int t   = threadIdx.x;
    float v = x[row * DIM + t];

    __shared__ float s1[8], s2[8];
    float a = v, b = v * v;
    #pragma unroll
    for (int o = 16; o > 0; o >>= 1) {
        a += __shfl_xor_sync(0xffffffffu, a, o);
        b += __shfl_xor_sync(0xffffffffu, b, o);
    }
    int lane = t & 31, w = t >> 5;
    if (lane == 0) { s1[w] = a; s2[w] = b; }
    __syncthreads();
    if (t == 0) {
        float sa = 0.f, sb = 0.f;
        #pragma unroll
        for (int i = 0; i < 8; i++) { sa += s1[i]; sb += s2[i]; }
        s1[0] = sa * (1.0f / DIM);
        s2[0] = sb * (1.0f / DIM);
    }
    __syncthreads();
    float mu  = s1[0];
    float var = s2[0] - mu * mu;
    float rr  = rsqrtf(var + LN_EPS);
    xn[row * DIM + t] = (v - mu) * rr * (gamma[t] + 1.0f);
}

// ---------------- fp32 -> bf16 hi/lo split (xn only) -------------------------
__global__ void split_kernel(const float* __restrict__ src,
                             __nv_bfloat16* __restrict__ hi,
                             __nv_bfloat16* __restrict__ lo,
                             long long n4)
{
    long long i = ((long long)blockIdx.x * blockDim.x + threadIdx.x);
    if (i >= n4) return;
    long long e = i * 4;
    float4 v = *(const float4*)(src + e);
    __nv_bfloat16 h0 = __float2bfloat16(v.x);
    __nv_bfloat16 h1 = __float2bfloat16(v.y);
    __nv_bfloat16 h2 = __float2bfloat16(v.z);
    __nv_bfloat16 h3 = __float2bfloat16(v.w);
    __nv_bfloat16 l0 = __float2bfloat16(v.x - __bfloat162float(h0));
    __nv_bfloat16 l1 = __float2bfloat16(v.y - __bfloat162float(h1));
    __nv_bfloat16 l2 = __float2bfloat16(v.z - __bfloat162float(h2));
    __nv_bfloat16 l3 = __float2bfloat16(v.w - __bfloat162float(h3));
    ((__nv_bfloat162*)(hi + e))[0] = __nv_bfloat162{h0, h1};
    ((__nv_bfloat162*)(hi + e))[1] = __nv_bfloat162{h2, h3};
    ((__nv_bfloat162*)(lo + e))[0] = __nv_bfloat162{l0, l1};
    ((__nv_bfloat162*)(lo + e))[1] = __nv_bfloat162{l2, l3};
}

// ---------------- split-K 64x64 GEMM for head precomputes --------------------
template<bool AT>
__global__ void __launch_bounds__(256)
gemm64_sk(const float* __restrict__ A, const float* __restrict__ B,
          float* __restrict__ Cp, int lda, int ldb)
{
    __shared__ float As[16][68];
    __shared__ float Bs[16][68];

    int z = blockIdx.z;
    int h = z / NSPLIT, sp = z % NSPLIT;
    long long hk0 = (long long)h * DHEAD + (long long)sp * KS;

    const float* Ab = AT ? (A + hk0 * lda) : (A + hk0);
    const float* Bb = B + hk0 * ldb;
    float* Cb = Cp + (long long)z * DIM * DIM;

    int m0 = blockIdx.y * 64;
    int n0 = blockIdx.x * 64;
    int tid = threadIdx.x;
    int tx = tid & 15;
    int ty = tid >> 4;

    float acc[4][4];
    #pragma unroll
    for (int i = 0; i < 4; i++)
        #pragma unroll
        for (int j = 0; j < 4; j++) acc[i][j] = 0.f;

    for (int k0 = 0; k0 < KS; k0 += 16) {
        if (AT) {
            int kk  = tid >> 4;
            int mm4 = (tid & 15) << 2;
            float4 a = *(const float4*)(Ab + (long long)(k0 + kk) * lda + m0 + mm4);
            *(float4*)&As[kk][mm4] = a;
        } else {
            int mm = tid >> 2;
            int kq = (tid & 3) << 2;
            float4 a = *(const float4*)(Ab + (long long)(m0 + mm) * lda + k0 + kq);
            As[kq + 0][mm] = a.x;
            As[kq + 1][mm] = a.y;
            As[kq + 2][mm] = a.z;
            As[kq + 3][mm] = a.w;
        }
        {
            int kk  = tid >> 4;
            int nn4 = (tid & 15) << 2;
            float4 b = *(const float4*)(Bb + (long long)(k0 + kk) * ldb + n0 + nn4);
            *(float4*)&Bs[kk][nn4] = b;
        }
        __syncthreads();

        #pragma unroll
        for (int kk = 0; kk < 16; kk++) {
            float4 ra = *(const float4*)&As[kk][ty * 4];
            float4 rb = *(const float4*)&Bs[kk][tx * 4];
            float va[4] = { ra.x, ra.y, ra.z, ra.w };
            float vb[4] = { rb.x, rb.y, rb.z, rb.w };
            #pragma unroll
            for (int i = 0; i < 4; i++)
                #pragma unroll
                for (int j = 0; j < 4; j++)
                    acc[i][j] = fmaf(va[i], vb[j], acc[i][j]);
        }
        __syncthreads();
    }

    #pragma unroll
    for (int i = 0; i < 4; i++)
        #pragma unroll
        for (int j = 0; j < 4; j++)
            Cb[(long long)(m0 + ty * 4 + i) * DIM + (n0 + tx * 4 + j)] = acc[i][j];
}

// ------------- reduce split-K partials -> bf16 hi/lo ------------------------
__global__ void reduce_split_kernel(const float* __restrict__ part,
                                    __nv_bfloat16* __restrict__ hi,
                                    __nv_bfloat16* __restrict__ lo)
{
    int idx = blockIdx.x * 256 + threadIdx.x;
    int h   = idx >> 16;
    int off = idx & 65535;
    const float* p = part + (long long)h * NSPLIT * 65536 + off;
    float acc = 0.f;
    #pragma unroll
    for (int s = 0; s < NSPLIT; s++) acc += p[(long long)s * 65536];
    __nv_bfloat16 hv = __float2bfloat16(acc);
    hi[idx] = hv;
    lo[idx] = __float2bfloat16(acc - __bfloat162float(hv));
}

// ---------------- reduce per-head partials ----------------------------------
__global__ void reduce_kernel(const float* __restrict__ op, float* __restrict__ out)
{
    int row = blockIdx.x;
    int t   = threadIdx.x;
    int b   = row >> 11;
    int q   = row & 2047;
    const float* base = op + (((long long)b * HEADS) * NTOK + q) * DIM + t;
    float acc = 0.f;
    #pragma unroll
    for (int h = 0; h < HEADS; h++)
        acc += base[(long long)h * NTOK * DIM];
    out[(long long)row * DIM + t] = acc;
}

// ---------------- launch ----------------------------------------------------
extern "C" void kernel_launch(void* const* d_in, const int* in_sizes, int n_in,
                              void* d_out, int out_size)
{
    const float* x     = (const float*)d_in[0];
    const float* gamma = (const float*)d_in[1];
    const float* Wq    = (const float*)d_in[2];
    const float* Wk    = (const float*)d_in[3];
    const float* Wv    = (const float*)d_in[4];
    const float* Wo    = (const float*)d_in[5];
    float* out = (float*)d_out;

    cudaFuncSetAttribute(mma_nt<OUT_F32>,   cudaFuncAttributeMaxDynamicSharedMemorySize, MM_SMEM);
    cudaFuncSetAttribute(mma_nt<OUT_SPLIT>, cudaFuncAttributeMaxDynamicSharedMemorySize, MM_SMEM);
    cudaFuncSetAttribute(mma_nt<OUT_EXP>,   cudaFuncAttributeMaxDynamicSharedMemorySize, MM_SMEM);
    cudaFuncSetAttribute(mma_nt<OUT_DIV>,   cudaFuncAttributeMaxDynamicSharedMemorySize, MM_SMEM);

    float *xn, *pm, *pg, *op, *sp, *ri;
    __nv_bfloat16 *xnh, *xnl, *mth, *mtl, *ghh, *ghl, *th, *tl, *uth, *utl, *eh, *el;
    cudaGetSymbolAddress((void**)&xn,  g_xn);
    cudaGetSymbolAddress((void**)&pm,  g_pm);
    cudaGetSymbolAddress((void**)&pg,  g_pg);
    cudaGetSymbolAddress((void**)&op,  g_op);
    cudaGetSymbolAddress((void**)&sp,  g_sp);
    cudaGetSymbolAddress((void**)&ri,  g_ri);
    cudaGetSymbolAddress((void**)&xnh, g_xnh);
    cudaGetSymbolAddress((void**)&xnl, g_xnl);
    cudaGetSymbolAddress((void**)&mth, g_mth);
    cudaGetSymbolAddress((void**)&mtl, g_mtl);
    cudaGetSymbolAddress((void**)&ghh, g_gh_);
    cudaGetSymbolAddress((void**)&ghl, g_gl_);
    cudaGetSymbolAddress((void**)&th,  g_th);
    cudaGetSymbolAddress((void**)&tl,  g_tl);
    cudaGetSymbolAddress((void**)&uth, g_uth);
    cudaGetSymbolAddress((void**)&utl, g_utl);
    cudaGetSymbolAddress((void**)&eh,  g_eh);
    cudaGetSymbolAddress((void**)&el,  g_el);

    const long long TD  = (long long)NTOK * DIM;
    const long long HTD = (long long)HEADS * TD;
    const long long SB  = (long long)NTOK * INNER;
    const long long DD  = (long long)DIM * DIM;

    // 1) LayerNorm + split xn
    ln_kernel<<<TOK, 256>>>(x, gamma, xn);
    split_kernel<<<(TOK * DIM / 4 + 255) / 256, 256>>>(xn, xnh, xnl, TOK * DIM / 4);

    // 2) precomputes (split-K): Mt_h = Wk_h^T Wq_h ; G_h = Wo_h Wv_h
    {
        dim3 grid(4, 4, HEADS * NSPLIT);
        gemm64_sk<true ><<<grid, 256>>>(Wk, Wq, pm, DIM, DIM);
        gemm64_sk<false><<<grid, 256>>>(Wo, Wv, pg, INNER, DIM);
        reduce_split_kernel<<<HEADS * DIM * DIM / 256, 256>>>(pm, mth, mtl);
        reduce_split_kernel<<<HEADS * DIM * DIM / 256, 256>>>(pg, ghh, ghl);
    }

    // 3) T[b][h] = xn_b * Mt_h^T  (NT, split-out epilogue)
    {
        dim3 grid(DIM / 128, NTOK / 128, BATCH * HEADS);
        mma_nt<OUT_SPLIT><<<grid, 256, MM_SMEM>>>(
            xnh, xnl, mth, mtl, nullptr, th, tl, nullptr, nullptr,
            DIM, DIM, DIM, DIM, HEADS,
            TD, 0, 0, DD, HTD, TD, 1.0f);
    }

    // 4) E = exp(scale * T * xn^T)  (NT, exp epilogue + row-sum partials)
    {
        dim3 grid(NTOK / 128, NTOK / 128, BATCH * HEADS);
        mma_nt<OUT_EXP><<<grid, 256, MM_SMEM>>>(
            th, tl, xnh, xnl, nullptr, eh, el, sp, nullptr,
            DIM, DIM, DIM, INNER, HEADS,
            HTD, TD, TD, 0, SB, (long long)DHEAD,
            ATT_SCALE);
    }

    // 5) rinv = 1 / rowsum
    rowsum_kernel<<<NROWS / 256, 256>>>(sp, ri);

    // 6) Ut[b][h] = G_h * xn_b^T  (NT, split-out epilogue)
    {
        dim3 grid(NTOK / 128, DIM / 128, BATCH * HEADS);
        mma_nt<OUT_SPLIT><<<grid, 256, MM_SMEM>>>(
            ghh, ghl, xnh, xnl, nullptr, uth, utl, nullptr, nullptr,
            DIM, DIM, DIM, NTOK, HEADS,
            0, DD, TD, 0, HTD, TD, 1.0f);
    }

    // 7) op[b][h] = (E[b][h] * Ut[b][h]^T) * rinv  (NT, div epilogue)
    {
        dim3 grid(DIM / 128, NTOK / 128, BATCH * HEADS);
        mma_nt<OUT_DIV><<<grid, 256, MM_SMEM>>>(
            eh, el, uth, utl, op, nullptr, nullptr, nullptr, ri,
            NTOK, INNER, NTOK, DIM, HEADS,
            SB, (long long)DHEAD, HTD, TD, HTD, TD,
            1.0f);
    }

    // 8) out = sum_h op[b][h]
    reduce_kernel<<<TOK, 256>>>(op, out);
}

// round 13
// speedup vs baseline: 1.7475x; 1.2297x over previous
#include <cuda_runtime.h>
#include <cuda_fp16.h>
#include <math.h>
#include <stdint.h>

// Problem constants (confirmed: inner = DIM_HEAD*dim = 16384)
#define BATCH   2
#define NTOK    2048
#define DIM     256
#define HEADS   8
#define INNER   16384
#define DHEAD   2048
#define TOK     (BATCH*NTOK)      // 4096
#define ATT_SCALE 0.125f
#define LN_EPS  1e-5f
#define NSPLIT  8
#define KS      (DHEAD/NSPLIT)    // 256
#define NTILES  (NTOK/128)        // 16 column tiles per head block
#define NROWS   (BATCH*HEADS*NTOK) // 32768 attention rows

// ---------------- scratch ---------------------------------------------------
__device__ float g_xn[TOK * DIM];
__device__ float g_pm[(size_t)HEADS * NSPLIT * DIM * DIM];
__device__ float g_pg[(size_t)HEADS * NSPLIT * DIM * DIM];
__device__ float g_op[(size_t)BATCH * HEADS * NTOK * DIM];
__device__ float g_sp[(size_t)NROWS * NTILES];   // row-sum partials
__device__ float g_ri[NROWS];                    // 1/rowsum

__device__ __half g_xnh[TOK * DIM];
__device__ __half g_xnl[TOK * DIM];              // A-side lo for T
__device__ __half g_mth[HEADS * DIM * DIM];      // B-side: hi only
__device__ __half g_gh_[HEADS * DIM * DIM];      // A-side hi for Ut
__device__ __half g_gl_[HEADS * DIM * DIM];      // A-side lo for Ut
__device__ __half g_th [(size_t)BATCH * HEADS * NTOK * DIM];  // A-side hi for S
__device__ __half g_tl [(size_t)BATCH * HEADS * NTOK * DIM];  // A-side lo for S
__device__ __half g_uth[(size_t)BATCH * HEADS * DIM * NTOK];  // B-side: hi
__device__ __half g_utl[(size_t)BATCH * HEADS * DIM * NTOK];  // lo written, unused
__device__ __half g_eh [(size_t)BATCH * NTOK * INNER];  // exp(logits) hi (A of PV)
__device__ __half g_el [(size_t)BATCH * NTOK * INNER];  // exp(logits) lo (A of PV)

// ---------------- asm helpers ------------------------------------------------
__device__ __forceinline__ uint32_t smem_u32(const void* p) {
    uint32_t a;
    asm("{ .reg .u64 tmp; cvta.to.shared.u64 tmp, %1; cvt.u32.u64 %0, tmp; }"
        : "=r"(a) : "l"(p));
    return a;
}
__device__ __forceinline__ void ldsm4u(uint32_t* d, uint32_t a)
{
    asm volatile("ldmatrix.sync.aligned.m8n8.x4.shared.b16 {%0,%1,%2,%3}, [%4];"
                 : "=r"(d[0]), "=r"(d[1]), "=r"(d[2]), "=r"(d[3]) : "r"(a));
}
__device__ __forceinline__ void mma_fp16(float* d, const uint32_t* a, const uint32_t* b)
{
    asm volatile(
        "mma.sync.aligned.m16n8k16.row.col.f32.f16.f16.f32 "
        "{%0,%1,%2,%3}, {%4,%5,%6,%7}, {%8,%9}, {%0,%1,%2,%3};"
        : "+f"(d[0]), "+f"(d[1]), "+f"(d[2]), "+f"(d[3])
        : "r"(a[0]), "r"(a[1]), "r"(a[2]), "r"(a[3]), "r"(b[0]), "r"(b[1]));
}
#define CP16(dst, src) \
    asm volatile("cp.async.cg.shared.global [%0], [%1], 16;" :: "r"(dst), "l"(src))
#define CP_COMMIT() asm volatile("cp.async.commit_group;" ::: "memory")
#define CP_WAIT0()  asm volatile("cp.async.wait_group 0;" ::: "memory")

// stage layout (bytes): 3 tiles of 128 rows x 40 fp16 (80B rows)
#define OFF_AH  0
#define OFF_AL  10240
#define OFF_BH  20480
#define STAGE   30720
#define MM_SMEM (2 * STAGE)

// mma_nt output modes
#define OUT_F32   0
#define OUT_SPLIT 1
#define OUT_EXP   2
#define OUT_DIV   3

// ---------------- fp16 2-pass tensor-core GEMM (NT), single-sync pipeline ---
// acc[m][n] = sum_k (Ahi*Bhi + Alo*Bhi)
template<int MODE>
__global__ void __launch_bounds__(256, 2)
mma_nt(const __half* __restrict__ Ahi, const __half* __restrict__ Alo,
       const __half* __restrict__ Bhi,
       float* __restrict__ C,
       __half* __restrict__ Chi, __half* __restrict__ Clo,
       float* __restrict__ Part, const float* __restrict__ Rinv,
       int K, int lda, int ldb, int ldc,
       int hdiv,
       long long sAb, long long sAh,
       long long sBb, long long sBh,
       long long sCb, long long sCh,
       float alpha)
{
    extern __shared__ __align__(16) char smem[];
    __shared__ float ssum[128][2];
    uint32_t sb = smem_u32(smem);

    int bz = blockIdx.z;
    int zb = bz / hdiv, zh = bz % hdiv;
    long long aoff = (long long)zb * sAb + (long long)zh * sAh;
    long long boff = (long long)zb * sBb + (long long)zh * sBh;
    long long coff = (long long)zb * sCb + (long long)zh * sCh;
    const __half* Ah = Ahi + aoff;
    const __half* Al = Alo + aoff;
    const __half* Bh = Bhi + boff;

    int m0 = blockIdx.y * 128;
    int n0 = blockIdx.x * 128;
    int tid  = threadIdx.x;
    int warp = tid >> 5;
    int lane = tid & 31;
    int wm = (warp & 3) * 32;
    int wn = (warp >> 2) * 64;

    int r  = tid >> 2;
    int kc = (tid & 3) * 8;

    float acc[2][8][4];
    #pragma unroll
    for (int i = 0; i < 2; i++)
        #pragma unroll
        for (int j = 0; j < 8; j++)
            #pragma unroll
            for (int c = 0; c < 4; c++) acc[i][j][c] = 0.f;

    const int NC = K / 32;

    auto load_stage = [&](int st, int k0) {
        uint32_t s0 = sb + (uint32_t)st * STAGE;
        #pragma unroll
        for (int i = 0; i < 2; i++) {
            int row = r + i * 64;
            uint32_t so = (uint32_t)row * 80 + (uint32_t)kc * 2;
            CP16(s0 + OFF_AH + so, Ah + (long long)(m0 + row) * lda + k0 + kc);
            CP16(s0 + OFF_AL + so, Al + (long long)(m0 + row) * lda + k0 + kc);
            CP16(s0 + OFF_BH + so, Bh + (long long)(n0 + row) * ldb + k0 + kc);
        }
    };

    load_stage(0, 0);
    CP_COMMIT();

    for (int i = 0; i < NC; i++) {
        CP_WAIT0();
        __syncthreads();
        if (i + 1 < NC) { load_stage((i + 1) & 1, (i + 1) * 32); CP_COMMIT(); }

        uint32_t base = sb + (uint32_t)(i & 1) * STAGE;

        #pragma unroll
        for (int s = 0; s < 32; s += 16) {
            uint32_t ah[2][4], al[2][4];
            #pragma unroll
            for (int ii = 0; ii < 2; ii++) {
                uint32_t ra = base + (uint32_t)(wm + ii * 16 + (lane & 15)) * 80
                            + (uint32_t)(s + ((lane >> 4) << 3)) * 2;
                ldsm4u(ah[ii], ra + OFF_AH);
                ldsm4u(al[ii], ra + OFF_AL);
            }
            #pragma unroll
            for (int j = 0; j < 4; j++) {
                uint32_t rb = base + (uint32_t)(wn + j * 16 + ((lane >> 4) << 3) + (lane & 7)) * 80
                            + (uint32_t)(s + ((lane >> 3) & 1) * 8) * 2;
                uint32_t bh[4];
                ldsm4u(bh, rb + OFF_BH);
                #pragma unroll
                for (int jj = 0; jj < 2; jj++) {
                    #pragma unroll
                    for (int ii = 0; ii < 2; ii++) {
                        mma_fp16(acc[ii][j * 2 + jj], ah[ii], bh + jj * 2);
                        mma_fp16(acc[ii][j * 2 + jj], al[ii], bh + jj * 2);
                    }
                }
            }
        }
    }

    // ---------------- epilogue ----------------
    float rowacc[2][2] = {{0.f, 0.f}, {0.f, 0.f}};
    float rv[2][2];
    if (MODE == OUT_DIV) {
        #pragma unroll
        for (int i = 0; i < 2; i++)
            #pragma unroll
            for (int hh = 0; hh < 2; hh++)
                rv[i][hh] = Rinv[(long long)bz * NTOK + m0 + wm + i * 16 + hh * 8 + (lane >> 2)];
    }

    #pragma unroll
    for (int i = 0; i < 2; i++) {
        #pragma unroll
        for (int j = 0; j < 8; j++) {
            int row = m0 + wm + i * 16 + (lane >> 2);
            int col = n0 + wn + j * 8 + (lane & 3) * 2;
            #pragma unroll
            for (int hh = 0; hh < 2; hh++) {
                long long off = coff + (long long)(row + hh * 8) * ldc + col;
                float v0 = acc[i][j][hh * 2 + 0];
                float v1 = acc[i][j][hh * 2 + 1];
                if (MODE == OUT_F32) {
                    float2 v = { alpha * v0, alpha * v1 };
                    *(float2*)(C + off) = v;
                } else if (MODE == OUT_SPLIT) {
                    v0 *= alpha; v1 *= alpha;
                    __half h0 = __float2half(v0);
                    __half h1 = __float2half(v1);
                    __half l0 = __float2half(v0 - __half2float(h0));
                    __half l1 = __float2half(v1 - __half2float(h1));
                    *(__half2*)(Chi + off) = __halves2half2(h0, h1);
                    *(__half2*)(Clo + off) = __halves2half2(l0, l1);
                } else if (MODE == OUT_EXP) {
                    float e0 = __expf(alpha * v0);
                    float e1 = __expf(alpha * v1);
                    __half h0 = __float2half(e0);
                    __half h1 = __float2half(e1);
                    __half l0 = __float2half(e0 - __half2float(h0));
                    __half l1 = __float2half(e1 - __half2float(h1));
                    *(__half2*)(Chi + off) = __halves2half2(h0, h1);
                    *(__half2*)(Clo + off) = __halves2half2(l0, l1);
                    rowacc[i][hh] += e0 + e1;
                } else { // OUT_DIV
                    float2 v = { rv[i][hh] * v0, rv[i][hh] * v1 };
                    *(float2*)(C + off) = v;
                }
            }
        }
    }

    if (MODE == OUT_EXP) {
        #pragma unroll
        for (int i = 0; i < 2; i++)
            #pragma unroll
            for (int hh = 0; hh < 2; hh++) {
                rowacc[i][hh] += __shfl_xor_sync(0xffffffffu, rowacc[i][hh], 1);
                rowacc[i][hh] += __shfl_xor_sync(0xffffffffu, rowacc[i][hh], 2);
            }
        if ((lane & 3) == 0) {
            #pragma unroll
            for (int i = 0; i < 2; i++)
                #pragma unroll
                for (int hh = 0; hh < 2; hh++)
                    ssum[wm + i * 16 + hh * 8 + (lane >> 2)][warp >> 2] = rowacc[i][hh];
        }
        __syncthreads();
        if (tid < 128) {
            float sp = ssum[tid][0] + ssum[tid][1];
            Part[((long long)bz * NTOK + m0 + tid) * NTILES + blockIdx.x] = sp;
        }
    }
}

// ---------------- rowsum -> reciprocal ---------------------------------------
__global__ void rowsum_kernel(const float* __restrict__ part, float* __restrict__ rinv)
{
    int idx = blockIdx.x * 256 + threadIdx.x;
    const float* p = part + (long long)idx * NTILES;
    float s = 0.f;
    #pragma unroll
    for (int i = 0; i < NTILES; i++) s += p[i];
    rinv[idx] = 1.0f / s;
}

// ---------------- LayerNorm -------------------------------------------------
__global__ void ln_kernel(const float* __restrict__ x,
                          const float* __restrict__ gamma,
                          float* __restrict__ xn)
{
    int row = blockIdx.x;
    int t   = threadIdx.x;
    float v = x[row * DIM + t];

    __shared__ float s1[8], s2[8];
    float a = v, b = v * v;
    #pragma unroll
    for (int o = 16; o > 0; o >>= 1) {
        a += __shfl_xor_sync(0xffffffffu, a, o);
        b += __shfl_xor_sync(0xffffffffu, b, o);
    }
    int lane = t & 31, w = t >> 5;
    if (lane == 0) { s1[w] = a; s2[w] = b; }
    __syncthreads();
    if (t == 0) {
        float sa = 0.f, sb = 0.f;
        #pragma unroll
        for (int i = 0; i < 8; i++) { sa += s1[i]; sb += s2[i]; }
        s1[0] = sa * (1.0f / DIM);
        s2[0] = sb * (1.0f / DIM);
    }
    __syncthreads();
    float mu  = s1[0];
    float var = s2[0] - mu * mu;
    float rr  = rsqrtf(var + LN_EPS);
    xn[row * DIM + t] = (v - mu) * rr * (gamma[t] + 1.0f);
}

// ---------------- fp32 -> fp16 hi/lo split (xn only) -------------------------
__global__ void split_kernel(const float* __restrict__ src,
                             __half* __restrict__ hi,
                             __half* __restrict__ lo,
                             long long n4)
{
    long long i = ((long long)blockIdx.x * blockDim.x + threadIdx.x);
    if (i >= n4) return;
    long long e = i * 4;
    float4 v = *(const float4*)(src + e);
    __half h0 = __float2half(v.x);
    __half h1 = __float2half(v.y);
    __half h2 = __float2half(v.z);
    __half h3 = __float2half(v.w);
    __half l0 = __float2half(v.x - __half2float(h0));
    __half l1 = __float2half(v.y - __half2float(h1));
    __half l2 = __float2half(v.z - __half2float(h2));
    __half l3 = __float2half(v.w - __half2float(h3));
    ((__half2*)(hi + e))[0] = __halves2half2(h0, h1);
    ((__half2*)(hi + e))[1] = __halves2half2(h2, h3);
    ((__half2*)(lo + e))[0] = __halves2half2(l0, l1);
    ((__half2*)(lo + e))[1] = __halves2half2(l2, l3);
}

// ---------------- split-K 64x64 GEMM for head precomputes --------------------
template<bool AT>
__global__ void __launch_bounds__(256)
gemm64_sk(const float* __restrict__ A, const float* __restrict__ B,
          float* __restrict__ Cp, int lda, int ldb)
{
    __shared__ float As[16][68];
    __shared__ float Bs[16][68];

    int z = blockIdx.z;
    int h = z / NSPLIT, sp = z % NSPLIT;
    long long hk0 = (long long)h * DHEAD + (long long)sp * KS;

    const float* Ab = AT ? (A + hk0 * lda) : (A + hk0);
    const float* Bb = B + hk0 * ldb;
    float* Cb = Cp + (long long)z * DIM * DIM;

    int m0 = blockIdx.y * 64;
    int n0 = blockIdx.x * 64;
    int tid = threadIdx.x;
    int tx = tid & 15;
    int ty = tid >> 4;

    float acc[4][4];
    #pragma unroll
    for (int i = 0; i < 4; i++)
        #pragma unroll
        for (int j = 0; j < 4; j++) acc[i][j] = 0.f;

    for (int k0 = 0; k0 < KS; k0 += 16) {
        if (AT) {
            int kk  = tid >> 4;
            int mm4 = (tid & 15) << 2;
            float4 a = *(const float4*)(Ab + (long long)(k0 + kk) * lda + m0 + mm4);
            *(float4*)&As[kk][mm4] = a;
        } else {
            int mm = tid >> 2;
            int kq = (tid & 3) << 2;
            float4 a = *(const float4*)(Ab + (long long)(m0 + mm) * lda + k0 + kq);
            As[kq + 0][mm] = a.x;
            As[kq + 1][mm] = a.y;
            As[kq + 2][mm] = a.z;
            As[kq + 3][mm] = a.w;
        }
        {
            int kk  = tid >> 4;
            int nn4 = (tid & 15) << 2;
            float4 b = *(const float4*)(Bb + (long long)(k0 + kk) * ldb + n0 + nn4);
            *(float4*)&Bs[kk][nn4] = b;
        }
        __syncthreads();

        #pragma unroll
        for (int kk = 0; kk < 16; kk++) {
            float4 ra = *(const float4*)&As[kk][ty * 4];
            float4 rb = *(const float4*)&Bs[kk][tx * 4];
            float va[4] = { ra.x, ra.y, ra.z, ra.w };
            float vb[4] = { rb.x, rb.y, rb.z, rb.w };
            #pragma unroll
            for (int i = 0; i < 4; i++)
                #pragma unroll
                for (int j = 0; j < 4; j++)
                    acc[i][j] = fmaf(va[i], vb[j], acc[i][j]);
        }
        __syncthreads();
    }

    #pragma unroll
    for (int i = 0; i < 4; i++)
        #pragma unroll
        for (int j = 0; j < 4; j++)
            Cb[(long long)(m0 + ty * 4 + i) * DIM + (n0 + tx * 4 + j)] = acc[i][j];
}

// ------------- reduce split-K partials -> fp16 hi/lo ------------------------
__global__ void reduce_split_kernel(const float* __restrict__ part,
                                    __half* __restrict__ hi,
                                    __half* __restrict__ lo)
{
    int idx = blockIdx.x * 256 + threadIdx.x;
    int h   = idx >> 16;
    int off = idx & 65535;
    const float* p = part + (long long)h * NSPLIT * 65536 + off;
    float acc = 0.f;
    #pragma unroll
    for (int s = 0; s < NSPLIT; s++) acc += p[(long long)s * 65536];
    __half hv = __float2half(acc);
    hi[idx] = hv;
    if (lo) lo[idx] = __float2half(acc - __half2float(hv));
}

// ---------------- reduce per-head partials ----------------------------------
__global__ void reduce_kernel(const float* __restrict__ op, float* __restrict__ out)
{
    int row = blockIdx.x;
    int t   = threadIdx.x;
    int b   = row >> 11;
    int q   = row & 2047;
    const float* base = op + (((long long)b * HEADS) * NTOK + q) * DIM + t;
    float acc = 0.f;
    #pragma unroll
    for (int h = 0; h < HEADS; h++)
        acc += base[(long long)h * NTOK * DIM];
    out[(long long)row * DIM + t] = acc;
}

// ---------------- launch ----------------------------------------------------
extern "C" void kernel_launch(void* const* d_in, const int* in_sizes, int n_in,
                              void* d_out, int out_size)
{
    const float* x     = (const float*)d_in[0];
    const float* gamma = (const float*)d_in[1];
    const float* Wq    = (const float*)d_in[2];
    const float* Wk    = (const float*)d_in[3];
    const float* Wv    = (const float*)d_in[4];
    const float* Wo    = (const float*)d_in[5];
    float* out = (float*)d_out;

    cudaFuncSetAttribute(mma_nt<OUT_F32>,   cudaFuncAttributeMaxDynamicSharedMemorySize, MM_SMEM);
    cudaFuncSetAttribute(mma_nt<OUT_SPLIT>, cudaFuncAttributeMaxDynamicSharedMemorySize, MM_SMEM);
    cudaFuncSetAttribute(mma_nt<OUT_EXP>,   cudaFuncAttributeMaxDynamicSharedMemorySize, MM_SMEM);
    cudaFuncSetAttribute(mma_nt<OUT_DIV>,   cudaFuncAttributeMaxDynamicSharedMemorySize, MM_SMEM);

    float *xn, *pm, *pg, *op, *sp, *ri;
    __half *xnh, *xnl, *mth, *ghh, *ghl, *th, *tl, *uth, *utl, *eh, *el;
    cudaGetSymbolAddress((void**)&xn,  g_xn);
    cudaGetSymbolAddress((void**)&pm,  g_pm);
    cudaGetSymbolAddress((void**)&pg,  g_pg);
    cudaGetSymbolAddress((void**)&op,  g_op);
    cudaGetSymbolAddress((void**)&sp,  g_sp);
    cudaGetSymbolAddress((void**)&ri,  g_ri);
    cudaGetSymbolAddress((void**)&xnh, g_xnh);
    cudaGetSymbolAddress((void**)&xnl, g_xnl);
    cudaGetSymbolAddress((void**)&mth, g_mth);
    cudaGetSymbolAddress((void**)&ghh, g_gh_);
    cudaGetSymbolAddress((void**)&ghl, g_gl_);
    cudaGetSymbolAddress((void**)&th,  g_th);
    cudaGetSymbolAddress((void**)&tl,  g_tl);
    cudaGetSymbolAddress((void**)&uth, g_uth);
    cudaGetSymbolAddress((void**)&utl, g_utl);
    cudaGetSymbolAddress((void**)&eh,  g_eh);
    cudaGetSymbolAddress((void**)&el,  g_el);

    const long long TD  = (long long)NTOK * DIM;
    const long long HTD = (long long)HEADS * TD;
    const long long SB  = (long long)NTOK * INNER;
    const long long DD  = (long long)DIM * DIM;

    // 1) LayerNorm + split xn
    ln_kernel<<<TOK, 256>>>(x, gamma, xn);
    split_kernel<<<(TOK * DIM / 4 + 255) / 256, 256>>>(xn, xnh, xnl, TOK * DIM / 4);

    // 2) precomputes (split-K): Mt_h = Wk_h^T Wq_h (hi only) ; G_h = Wo_h Wv_h (hi+lo)
    {
        dim3 grid(4, 4, HEADS * NSPLIT);
        gemm64_sk<true ><<<grid, 256>>>(Wk, Wq, pm, DIM, DIM);
        gemm64_sk<false><<<grid, 256>>>(Wo, Wv, pg, INNER, DIM);
        reduce_split_kernel<<<HEADS * DIM * DIM / 256, 256>>>(pm, mth, nullptr);
        reduce_split_kernel<<<HEADS * DIM * DIM / 256, 256>>>(pg, ghh, ghl);
    }

    // 3) T[b][h] = xn_b * Mt_h^T   (A = xn hi/lo, B = Mt hi; split-out)
    {
        dim3 grid(DIM / 128, NTOK / 128, BATCH * HEADS);
        mma_nt<OUT_SPLIT><<<grid, 256, MM_SMEM>>>(
            xnh, xnl, mth, nullptr, th, tl, nullptr, nullptr,
            DIM, DIM, DIM, DIM, HEADS,
            TD, 0, 0, DD, HTD, TD, 1.0f);
    }

    // 4) E = exp(scale * T * xn^T)  (A = T hi/lo, B = xn hi; exp + row sums)
    {
        dim3 grid(NTOK / 128, NTOK / 128, BATCH * HEADS);
        mma_nt<OUT_EXP><<<grid, 256, MM_SMEM>>>(
            th, tl, xnh, nullptr, eh, el, sp, nullptr,
            DIM, DIM, DIM, INNER, HEADS,
            HTD, TD, TD, 0, SB, (long long)DHEAD,
            ATT_SCALE);
    }

    // 5) rinv = 1 / rowsum
    rowsum_kernel<<<NROWS / 256, 256>>>(sp, ri);

    // 6) Ut[b][h] = G_h * xn_b^T  (A = G hi/lo, B = xn hi; hi used downstream, lo scratch)
    {
        dim3 grid(NTOK / 128, DIM / 128, BATCH * HEADS);
        mma_nt<OUT_SPLIT><<<grid, 256, MM_SMEM>>>(
            ghh, ghl, xnh, nullptr, uth, utl, nullptr, nullptr,
            DIM, DIM, DIM, NTOK, HEADS,
            0, DD, TD, 0, HTD, TD, 1.0f);
    }

    // 7) op[b][h] = (E[b][h] * Ut[b][h]^T) * rinv  (A = E hi/lo, B = Ut hi; div epilogue)
    {
        dim3 grid(DIM / 128, NTOK / 128, BATCH * HEADS);
        mma_nt<OUT_DIV><<<grid, 256, MM_SMEM>>>(
            eh, el, uth, op, nullptr, nullptr, nullptr, ri,
            NTOK, INNER, NTOK, DIM, HEADS,
            SB, (long long)DHEAD, HTD, TD, HTD, TD,
            1.0f);
    }

    // 8) out = sum_h op[b][h]
    reduce_kernel<<<TOK, 256>>>(op, out);
}

// round 14
// speedup vs baseline: 2.7706x; 1.5854x over previous
#include <cuda_runtime.h>
#include <cuda_fp16.h>
#include <math.h>
#include <stdint.h>

// Problem constants (confirmed: inner = DIM_HEAD*dim = 16384)
#define BATCH   2
#define NTOK    2048
#define DIM     256
#define HEADS   8
#define INNER   16384
#define DHEAD   2048
#define TOK     (BATCH*NTOK)      // 4096
#define ATT_SCALE 0.125f
#define LN_EPS  1e-5f
#define NSPLIT  8
#define KS      (DHEAD/NSPLIT)    // 256
#define NTILES  (NTOK/128)        // 16 column tiles per head block
#define NROWS   (BATCH*HEADS*NTOK) // 32768 attention rows

// ---------------- scratch ---------------------------------------------------
__device__ float g_xn[TOK * DIM];
__device__ float g_pm[(size_t)HEADS * NSPLIT * DIM * DIM];
__device__ float g_pg[(size_t)HEADS * NSPLIT * DIM * DIM];
__device__ float g_op[(size_t)BATCH * HEADS * NTOK * DIM];
__device__ float g_sp[(size_t)NROWS * NTILES];   // row-sum partials
__device__ float g_ri[NROWS];                    // 1/rowsum

__device__ __half g_xnh[TOK * DIM];
__device__ __half g_mth[HEADS * DIM * DIM];
__device__ __half g_ghh[HEADS * DIM * DIM];
__device__ __half g_th [(size_t)BATCH * HEADS * NTOK * DIM];
__device__ __half g_uth[(size_t)BATCH * HEADS * DIM * NTOK];
__device__ __half g_eh [(size_t)BATCH * NTOK * INNER];

// ---------------- asm helpers ------------------------------------------------
__device__ __forceinline__ uint32_t smem_u32(const void* p) {
    uint32_t a;
    asm("{ .reg .u64 tmp; cvta.to.shared.u64 tmp, %1; cvt.u32.u64 %0, tmp; }"
        : "=r"(a) : "l"(p));
    return a;
}
__device__ __forceinline__ void ldsm4u(uint32_t* d, uint32_t a)
{
    asm volatile("ldmatrix.sync.aligned.m8n8.x4.shared.b16 {%0,%1,%2,%3}, [%4];"
                 : "=r"(d[0]), "=r"(d[1]), "=r"(d[2]), "=r"(d[3]) : "r"(a));
}
__device__ __forceinline__ void mma_fp16(float* d, const uint32_t* a, const uint32_t* b)
{
    asm volatile(
        "mma.sync.aligned.m16n8k16.row.col.f32.f16.f16.f32 "
        "{%0,%1,%2,%3}, {%4,%5,%6,%7}, {%8,%9}, {%0,%1,%2,%3};"
        : "+f"(d[0]), "+f"(d[1]), "+f"(d[2]), "+f"(d[3])
        : "r"(a[0]), "r"(a[1]), "r"(a[2]), "r"(a[3]), "r"(b[0]), "r"(b[1]));
}
#define CP16(dst, src) \
    asm volatile("cp.async.cg.shared.global [%0], [%1], 16;" :: "r"(dst), "l"(src))
#define CP_COMMIT() asm volatile("cp.async.commit_group;" ::: "memory")
#define CP_WAIT0()  asm volatile("cp.async.wait_group 0;" ::: "memory")

// stage layout (bytes): 2 tiles of 128 rows x 40 fp16 (80B rows)
#define OFF_AH  0
#define OFF_BH  10240
#define STAGE   20480
#define MM_SMEM (2 * STAGE)

// mma_nt output modes
#define OUT_F32   0   // C = alpha * acc                (fp32)
#define OUT_F16   1   // Chi = fp16(alpha * acc)
#define OUT_EXP   2   // Chi = fp16(exp(alpha*acc)), + row-sum partials
#define OUT_DIV   3   // C = rinv[row] * acc            (fp32)

// ---------------- fp16 tensor-core GEMM (NT), single-sync pipeline ----------
// acc[m][n] = sum_k A[m][k]*B[n][k]   (both fp16, fp32 accum)
// Block 128x128, 8 warps of 32x64, k32 chunks.
template<int MODE>
__global__ void __launch_bounds__(256, 2)
mma_nt(const __half* __restrict__ A, const __half* __restrict__ B,
       float* __restrict__ C, __half* __restrict__ Chi,
       float* __restrict__ Part, const float* __restrict__ Rinv,
       int K, int lda, int ldb, int ldc,
       int hdiv,
       long long sAb, long long sAh,
       long long sBb, long long sBh,
       long long sCb, long long sCh,
       float alpha)
{
    extern __shared__ __align__(16) char smem[];
    __shared__ float ssum[128][2];
    uint32_t sb = smem_u32(smem);

    int bz = blockIdx.z;
    int zb = bz / hdiv, zh = bz % hdiv;
    const __half* Ab = A + (long long)zb * sAb + (long long)zh * sAh;
    const __half* Bb = B + (long long)zb * sBb + (long long)zh * sBh;
    long long coff = (long long)zb * sCb + (long long)zh * sCh;

    int m0 = blockIdx.y * 128;
    int n0 = blockIdx.x * 128;
    int tid  = threadIdx.x;
    int warp = tid >> 5;
    int lane = tid & 31;
    int wm = (warp & 3) * 32;
    int wn = (warp >> 2) * 64;

    int r  = tid >> 2;            // 0..63 (rows r and r+64)
    int kc = (tid & 3) * 8;       // k element offset (16B)

    float acc[2][8][4];
    #pragma unroll
    for (int i = 0; i < 2; i++)
        #pragma unroll
        for (int j = 0; j < 8; j++)
            #pragma unroll
            for (int c = 0; c < 4; c++) acc[i][j][c] = 0.f;

    const int NC = K / 32;

    auto load_stage = [&](int st, int k0) {
        uint32_t s0 = sb + (uint32_t)st * STAGE;
        #pragma unroll
        for (int i = 0; i < 2; i++) {
            int row = r + i * 64;
            uint32_t so = (uint32_t)row * 80 + (uint32_t)kc * 2;
            CP16(s0 + OFF_AH + so, Ab + (long long)(m0 + row) * lda + k0 + kc);
            CP16(s0 + OFF_BH + so, Bb + (long long)(n0 + row) * ldb + k0 + kc);
        }
    };

    load_stage(0, 0);
    CP_COMMIT();

    for (int i = 0; i < NC; i++) {
        CP_WAIT0();
        __syncthreads();          // proves compute(i-1) done -> buffer (i+1)&1 reusable
        if (i + 1 < NC) { load_stage((i + 1) & 1, (i + 1) * 32); CP_COMMIT(); }

        uint32_t base = sb + (uint32_t)(i & 1) * STAGE;

        #pragma unroll
        for (int s = 0; s < 32; s += 16) {
            uint32_t ah[2][4];
            #pragma unroll
            for (int ii = 0; ii < 2; ii++) {
                uint32_t ra = base + (uint32_t)(wm + ii * 16 + (lane & 15)) * 80
                            + (uint32_t)(s + ((lane >> 4) << 3)) * 2;
                ldsm4u(ah[ii], ra + OFF_AH);
            }
            #pragma unroll
            for (int j = 0; j < 4; j++) {
                uint32_t rb = base + (uint32_t)(wn + j * 16 + ((lane >> 4) << 3) + (lane & 7)) * 80
                            + (uint32_t)(s + ((lane >> 3) & 1) * 8) * 2;
                uint32_t bh[4];
                ldsm4u(bh, rb + OFF_BH);
                #pragma unroll
                for (int jj = 0; jj < 2; jj++)
                    #pragma unroll
                    for (int ii = 0; ii < 2; ii++)
                        mma_fp16(acc[ii][j * 2 + jj], ah[ii], bh + jj * 2);
            }
        }
    }

    // ---------------- epilogue ----------------
    float rowacc[2][2] = {{0.f, 0.f}, {0.f, 0.f}};
    float rv[2][2];
    if (MODE == OUT_DIV) {
        #pragma unroll
        for (int i = 0; i < 2; i++)
            #pragma unroll
            for (int hh = 0; hh < 2; hh++)
                rv[i][hh] = Rinv[(long long)bz * NTOK + m0 + wm + i * 16 + hh * 8 + (lane >> 2)];
    }

    #pragma unroll
    for (int i = 0; i < 2; i++) {
        #pragma unroll
        for (int j = 0; j < 8; j++) {
            int row = m0 + wm + i * 16 + (lane >> 2);
            int col = n0 + wn + j * 8 + (lane & 3) * 2;
            #pragma unroll
            for (int hh = 0; hh < 2; hh++) {
                long long off = coff + (long long)(row + hh * 8) * ldc + col;
                float v0 = acc[i][j][hh * 2 + 0];
                float v1 = acc[i][j][hh * 2 + 1];
                if (MODE == OUT_F32) {
                    float2 v = { alpha * v0, alpha * v1 };
                    *(float2*)(C + off) = v;
                } else if (MODE == OUT_F16) {
                    *(__half2*)(Chi + off) =
                        __halves2half2(__float2half(alpha * v0), __float2half(alpha * v1));
                } else if (MODE == OUT_EXP) {
                    float e0 = __expf(alpha * v0);
                    float e1 = __expf(alpha * v1);
                    *(__half2*)(Chi + off) =
                        __halves2half2(__float2half(e0), __float2half(e1));
                    rowacc[i][hh] += e0 + e1;
                } else { // OUT_DIV
                    float2 v = { rv[i][hh] * v0, rv[i][hh] * v1 };
                    *(float2*)(C + off) = v;
                }
            }
        }
    }

    if (MODE == OUT_EXP) {
        #pragma unroll
        for (int i = 0; i < 2; i++)
            #pragma unroll
            for (int hh = 0; hh < 2; hh++) {
                rowacc[i][hh] += __shfl_xor_sync(0xffffffffu, rowacc[i][hh], 1);
                rowacc[i][hh] += __shfl_xor_sync(0xffffffffu, rowacc[i][hh], 2);
            }
        if ((lane & 3) == 0) {
            #pragma unroll
            for (int i = 0; i < 2; i++)
                #pragma unroll
                for (int hh = 0; hh < 2; hh++)
                    ssum[wm + i * 16 + hh * 8 + (lane >> 2)][warp >> 2] = rowacc[i][hh];
        }
        __syncthreads();
        if (tid < 128) {
            float sp = ssum[tid][0] + ssum[tid][1];
            Part[((long long)bz * NTOK + m0 + tid) * NTILES + blockIdx.x] = sp;
        }
    }
}

// ---------------- rowsum -> reciprocal ---------------------------------------
__global__ void rowsum_kernel(const float* __restrict__ part, float* __restrict__ rinv)
{
    int idx = blockIdx.x * 256 + threadIdx.x;
    const float* p = part + (long long)idx * NTILES;
    float s = 0.f;
    #pragma unroll
    for (int i = 0; i < NTILES; i++) s += p[i];
    rinv[idx] = 1.0f / s;
}

// ---------------- LayerNorm -------------------------------------------------
__global__ void ln_kernel(const float* __restrict__ x,
                          const float* __restrict__ gamma,
                          float* __restrict__ xn,
                          __half* __restrict__ xnh)
{
    int row = blockIdx.x;
    int t   = threadIdx.x;
    float v = x[row * DIM + t];

    __shared__ float s1[8], s2[8];
    float a = v, b = v * v;
    #pragma unroll
    for (int o = 16; o > 0; o >>= 1) {
        a += __shfl_xor_sync(0xffffffffu, a, o);
        b += __shfl_xor_sync(0xffffffffu, b, o);
    }
    int lane = t & 31, w = t >> 5;
    if (lane == 0) { s1[w] = a; s2[w] = b; }
    __syncthreads();
    if (t == 0) {
        float sa = 0.f, sb = 0.f;
        #pragma unroll
        for (int i = 0; i < 8; i++) { sa += s1[i]; sb += s2[i]; }
        s1[0] = sa * (1.0f / DIM);
        s2[0] = sb * (1.0f / DIM);
    }
    __syncthreads();
    float mu  = s1[0];
    float var = s2[0] - mu * mu;
    float rr  = rsqrtf(var + LN_EPS);
    float o = (v - mu) * rr * (gamma[t] + 1.0f);
    xn [row * DIM + t] = o;
    xnh[row * DIM + t] = __float2half(o);
}

// ---------------- combined split-K 64x64 precompute GEMM --------------------
// z in [0, HEADS*NSPLIT)          : Mt partial = Wk_h^T * Wq_h     (TN)
// z in [HEADS*NSPLIT, 2*H*NSPLIT) : G  partial = Wo_h  * Wv_h      (NN)
__global__ void __launch_bounds__(256)
gemm64_pre(const float* __restrict__ Wk, const float* __restrict__ Wq,
           const float* __restrict__ Wo, const float* __restrict__ Wv,
           float* __restrict__ pm, float* __restrict__ pg)
{
    __shared__ float As[16][68];
    __shared__ float Bs[16][68];

    int z = blockIdx.z;
    bool isG = z >= HEADS * NSPLIT;
    int zz = isG ? z - HEADS * NSPLIT : z;
    int h = zz / NSPLIT, sp = zz % NSPLIT;
    long long hk0 = (long long)h * DHEAD + (long long)sp * KS;

    const float* Ab = isG ? (Wo + hk0) : (Wk + hk0 * DIM);
    const float* Bb = (isG ? Wv : Wq) + hk0 * DIM;
    int lda = isG ? INNER : DIM;
    float* Cb = (isG ? pg : pm) + (long long)zz * DIM * DIM;

    int m0 = blockIdx.y * 64;
    int n0 = blockIdx.x * 64;
    int tid = threadIdx.x;
    int tx = tid & 15;
    int ty = tid >> 4;

    float acc[4][4];
    #pragma unroll
    for (int i = 0; i < 4; i++)
        #pragma unroll
        for (int j = 0; j < 4; j++) acc[i][j] = 0.f;

    for (int k0 = 0; k0 < KS; k0 += 16) {
        if (!isG) {
            // TN: A is (K, M) row-major
            int kk  = tid >> 4;
            int mm4 = (tid & 15) << 2;
            float4 a = *(const float4*)(Ab + (long long)(k0 + kk) * lda + m0 + mm4);
            *(float4*)&As[kk][mm4] = a;
        } else {
            // NN: A is (M, K) row-major, transpose into As
            int mm = tid >> 2;
            int kq = (tid & 3) << 2;
            float4 a = *(const float4*)(Ab + (long long)(m0 + mm) * lda + k0 + kq);
            As[kq + 0][mm] = a.x;
            As[kq + 1][mm] = a.y;
            As[kq + 2][mm] = a.z;
            As[kq + 3][mm] = a.w;
        }
        {
            int kk  = tid >> 4;
            int nn4 = (tid & 15) << 2;
            float4 b = *(const float4*)(Bb + (long long)(k0 + kk) * DIM + n0 + nn4);
            *(float4*)&Bs[kk][nn4] = b;
        }
        __syncthreads();

        #pragma unroll
        for (int kk = 0; kk < 16; kk++) {
            float4 ra = *(const float4*)&As[kk][ty * 4];
            float4 rb = *(const float4*)&Bs[kk][tx * 4];
            float va[4] = { ra.x, ra.y, ra.z, ra.w };
            float vb[4] = { rb.x, rb.y, rb.z, rb.w };
            #pragma unroll
            for (int i = 0; i < 4; i++)
                #pragma unroll
                for (int j = 0; j < 4; j++)
                    acc[i][j] = fmaf(va[i], vb[j], acc[i][j]);
        }
        __syncthreads();
    }

    #pragma unroll
    for (int i = 0; i < 4; i++)
        #pragma unroll
        for (int j = 0; j < 4; j++)
            Cb[(long long)(m0 + ty * 4 + i) * DIM + (n0 + tx * 4 + j)] = acc[i][j];
}

// ------------- reduce split-K partials (both Mt and G) -> fp16 --------------
__global__ void reduce_pre_kernel(const float* __restrict__ pm,
                                  const float* __restrict__ pg,
                                  __half* __restrict__ mth,
                                  __half* __restrict__ ghh)
{
    int gi = blockIdx.x * 256 + threadIdx.x;          // over 2*HEADS*DIM*DIM
    bool isG = gi >= HEADS * DIM * DIM;
    int idx = isG ? gi - HEADS * DIM * DIM : gi;
    int h   = idx >> 16;
    int off = idx & 65535;
    const float* p = (isG ? pg : pm) + (long long)h * NSPLIT * 65536 + off;
    float acc = 0.f;
    #pragma unroll
    for (int s = 0; s < NSPLIT; s++) acc += p[(long long)s * 65536];
    (isG ? ghh : mth)[idx] = __float2half(acc);
}

// ---------------- reduce per-head partials ----------------------------------
__global__ void reduce_kernel(const float* __restrict__ op, float* __restrict__ out)
{
    int row = blockIdx.x;
    int t   = threadIdx.x;
    int b   = row >> 11;
    int q   = row & 2047;
    const float* base = op + (((long long)b * HEADS) * NTOK + q) * DIM + t;
    float acc = 0.f;
    #pragma unroll
    for (int h = 0; h < HEADS; h++)
        acc += base[(long long)h * NTOK * DIM];
    out[(long long)row * DIM + t] = acc;
}

// ---------------- launch ----------------------------------------------------
extern "C" void kernel_launch(void* const* d_in, const int* in_sizes, int n_in,
                              void* d_out, int out_size)
{
    const float* x     = (const float*)d_in[0];
    const float* gamma = (const float*)d_in[1];
    const float* Wq    = (const float*)d_in[2];
    const float* Wk    = (const float*)d_in[3];
    const float* Wv    = (const float*)d_in[4];
    const float* Wo    = (const float*)d_in[5];
    float* out = (float*)d_out;

    cudaFuncSetAttribute(mma_nt<OUT_F32>, cudaFuncAttributeMaxDynamicSharedMemorySize, MM_SMEM);
    cudaFuncSetAttribute(mma_nt<OUT_F16>, cudaFuncAttributeMaxDynamicSharedMemorySize, MM_SMEM);
    cudaFuncSetAttribute(mma_nt<OUT_EXP>, cudaFuncAttributeMaxDynamicSharedMemorySize, MM_SMEM);
    cudaFuncSetAttribute(mma_nt<OUT_DIV>, cudaFuncAttributeMaxDynamicSharedMemorySize, MM_SMEM);

    float *xn, *pm, *pg, *op, *sp, *ri;
    __half *xnh, *mth, *ghh, *th, *uth, *eh;
    cudaGetSymbolAddress((void**)&xn,  g_xn);
    cudaGetSymbolAddress((void**)&pm,  g_pm);
    cudaGetSymbolAddress((void**)&pg,  g_pg);
    cudaGetSymbolAddress((void**)&op,  g_op);
    cudaGetSymbolAddress((void**)&sp,  g_sp);
    cudaGetSymbolAddress((void**)&ri,  g_ri);
    cudaGetSymbolAddress((void**)&xnh, g_xnh);
    cudaGetSymbolAddress((void**)&mth, g_mth);
    cudaGetSymbolAddress((void**)&ghh, g_ghh);
    cudaGetSymbolAddress((void**)&th,  g_th);
    cudaGetSymbolAddress((void**)&uth, g_uth);
    cudaGetSymbolAddress((void**)&eh,  g_eh);

    const long long TD  = (long long)NTOK * DIM;
    const long long HTD = (long long)HEADS * TD;
    const long long SB  = (long long)NTOK * INNER;
    const long long DD  = (long long)DIM * DIM;

    // 1) LayerNorm (+fp16 quantize fused)
    ln_kernel<<<TOK, 256>>>(x, gamma, xn, xnh);

    // 2) combined precomputes: Mt_h = Wk_h^T Wq_h ; G_h = Wo_h Wv_h
    {
        dim3 grid(4, 4, 2 * HEADS * NSPLIT);
        gemm64_pre<<<grid, 256>>>(Wk, Wq, Wo, Wv, pm, pg);
        reduce_pre_kernel<<<2 * HEADS * DIM * DIM / 256, 256>>>(pm, pg, mth, ghh);
    }

    // 3) T[b][h] = xn_b * Mt_h^T
    {
        dim3 grid(DIM / 128, NTOK / 128, BATCH * HEADS);
        mma_nt<OUT_F16><<<grid, 256, MM_SMEM>>>(
            xnh, mth, nullptr, th, nullptr, nullptr,
            DIM, DIM, DIM, DIM, HEADS,
            TD, 0, 0, DD, HTD, TD, 1.0f);
    }

    // 4) E = exp(scale * T * xn^T)  (+ row-sum partials)
    {
        dim3 grid(NTOK / 128, NTOK / 128, BATCH * HEADS);
        mma_nt<OUT_EXP><<<grid, 256, MM_SMEM>>>(
            th, xnh, nullptr, eh, sp, nullptr,
            DIM, DIM, DIM, INNER, HEADS,
            HTD, TD, TD, 0, SB, (long long)DHEAD,
            ATT_SCALE);
    }

    // 5) rinv = 1 / rowsum
    rowsum_kernel<<<NROWS / 256, 256>>>(sp, ri);

    // 6) Ut[b][h] = G_h * xn_b^T
    {
        dim3 grid(NTOK / 128, DIM / 128, BATCH * HEADS);
        mma_nt<OUT_F16><<<grid, 256, MM_SMEM>>>(
            ghh, xnh, nullptr, uth, nullptr, nullptr,
            DIM, DIM, DIM, NTOK, HEADS,
            0, DD, TD, 0, HTD, TD, 1.0f);
    }

    // 7) op[b][h] = (E[b][h] * Ut[b][h]^T) * rinv
    {
        dim3 grid(DIM / 128, NTOK / 128, BATCH * HEADS);
        mma_nt<OUT_DIV><<<grid, 256, MM_SMEM>>>(
            eh, uth, op, nullptr, nullptr, ri,
            NTOK, INNER, NTOK, DIM, HEADS,
            SB, (long long)DHEAD, HTD, TD, HTD, TD,
            1.0f);
    }

    // 8) out = sum_h op[b][h]
    reduce_kernel<<<TOK, 256>>>(op, out);
}